// round 3
// baseline (speedup 1.0000x reference)
#include <cuda_runtime.h>

// ---------------- problem constants ----------------
#define CB   2
#define CS   2048
#define CD   1024
#define CH   16
#define CDK  64
#define CDV  64
#define CSEG 512
#define CSL  128
#define CL   768          // SL + SEG + SL
#define CBH  32           // B*H
#define C2DV 128          // 2*DV (= 2*DK)

// ---------------- scratch (device globals; no allocations allowed) ----------
__device__ float g_kf[CB*CH*CS*CDK];      // [B][H][S][64]
__device__ float g_qf[CB*CH*CS*CDK];
__device__ float g_vf[CB*CH*CS*CDV];
__device__ float g_state[CB*CSL*CD];      // [B][128][1024]
__device__ float g_kk[CBH*CL*CDK];        // [z=b*H+h][768][64]
__device__ float g_qq[CBH*CL*CDK];
__device__ float g_vv[CBH*CL*CDV];
__device__ float g_s1[CBH*CL*CL];         // scores scratch (reused for both attns)
__device__ float g_att1[CBH*CL*CDV];      // [z][768][64]
__device__ float g_k2[CBH*CL*C2DV];       // [z][768][128]
__device__ float g_q2[CBH*CL*C2DV];
__device__ float g_v2[CBH*CL*C2DV];
__device__ float g_a2c[CB*CH*CSEG*C2DV];  // compact att2 middle -> per-b [512 x 2048] view
__device__ float g_a2e[CB*CH*CSL*C2DV];   // compact att2 end    -> per-b [128 x 2048] view

// ---------------- generic tiled SGEMM (NN): C = scale * A(MxK) @ B(KxN) -----
// batched over z: b=z/nh, h=z%nh; A += b*sAb+h*sAh; B += b*sBb+h*sBh; C += z*sC
// split store: local rows r<splitRow -> C, else -> C2 (row r-splitRow)
__global__ void __launch_bounds__(256) sgemm_nn(
    int K,
    const float* __restrict__ A, int lda, long sAb, long sAh,
    const float* __restrict__ B, int ldb, long sBb, long sBh,
    float* __restrict__ C, int ldc, long sC,
    float* __restrict__ C2, int ldc2, long sC2, int splitRow,
    float scale, int nh)
{
    int z = blockIdx.z, b = z / nh, h = z - b * nh;
    A += (long)b * sAb + (long)h * sAh;
    B += (long)b * sBb + (long)h * sBh;
    C += (long)z * sC;
    if (C2) C2 += (long)z * sC2;

    __shared__ float As[64][16];
    __shared__ float Bs[16][64];

    int tid = threadIdx.x;
    int tr = tid >> 4, tc = tid & 15;
    int row0 = blockIdx.x * 64, col0 = blockIdx.y * 64;
    int am = tid >> 2, ak = (tid & 3) << 2;   // A tile: 64 rows x 16 k
    int bk = tid >> 4, bn = (tid & 15) << 2;  // B tile: 16 k x 64 cols

    float acc[4][4];
#pragma unroll
    for (int i = 0; i < 4; i++)
#pragma unroll
        for (int j = 0; j < 4; j++) acc[i][j] = 0.f;

    const float* Ap = A + (long)(row0 + am) * lda + ak;
    const float* Bp = B + (long)bk * ldb + col0 + bn;

    for (int k0 = 0; k0 < K; k0 += 16) {
        float4 av = *(const float4*)(Ap + k0);
        float4 bv = *(const float4*)(Bp + (long)k0 * ldb);
        *(float4*)&As[am][ak] = av;
        *(float4*)&Bs[bk][bn] = bv;
        __syncthreads();
#pragma unroll
        for (int kk = 0; kk < 16; kk++) {
            float a0 = As[tr * 4 + 0][kk];
            float a1 = As[tr * 4 + 1][kk];
            float a2 = As[tr * 4 + 2][kk];
            float a3 = As[tr * 4 + 3][kk];
            float4 bq = *(float4*)&Bs[kk][tc << 2];
            acc[0][0] += a0 * bq.x; acc[0][1] += a0 * bq.y; acc[0][2] += a0 * bq.z; acc[0][3] += a0 * bq.w;
            acc[1][0] += a1 * bq.x; acc[1][1] += a1 * bq.y; acc[1][2] += a1 * bq.z; acc[1][3] += a1 * bq.w;
            acc[2][0] += a2 * bq.x; acc[2][1] += a2 * bq.y; acc[2][2] += a2 * bq.z; acc[2][3] += a2 * bq.w;
            acc[3][0] += a3 * bq.x; acc[3][1] += a3 * bq.y; acc[3][2] += a3 * bq.z; acc[3][3] += a3 * bq.w;
        }
        __syncthreads();
    }

    int c0 = col0 + (tc << 2);
#pragma unroll
    for (int i = 0; i < 4; i++) {
        int r = row0 + tr * 4 + i;
        float4 v;
        v.x = acc[i][0] * scale; v.y = acc[i][1] * scale;
        v.z = acc[i][2] * scale; v.w = acc[i][3] * scale;
        if (r < splitRow) *(float4*)&C[(long)r * ldc + c0] = v;
        else              *(float4*)&C2[(long)(r - splitRow) * ldc2 + c0] = v;
    }
}

// ---------------- generic tiled SGEMM (NT): C = scale * A(MxK) @ B(NxK)^T ---
// fused causal mask: key (col0+c) > query (maskRowOff + row0 + r)  ->  -1e30
__global__ void __launch_bounds__(256) sgemm_nt(
    int K,
    const float* __restrict__ A, int lda, long sA,
    const float* __restrict__ B, int ldb, long sB,
    float* __restrict__ C, int ldc, long sC,
    float scale, int causal, int maskRowOff)
{
    int z = blockIdx.z;
    A += (long)z * sA; B += (long)z * sB; C += (long)z * sC;

    __shared__ float As[64][16];
    __shared__ float Bs[16][65];

    int tid = threadIdx.x;
    int tr = tid >> 4, tc = tid & 15;
    int row0 = blockIdx.x * 64, col0 = blockIdx.y * 64;
    int am = tid >> 2, ak = (tid & 3) << 2;
    int bn = tid >> 2, bk = (tid & 3) << 2;

    float acc[4][4];
#pragma unroll
    for (int i = 0; i < 4; i++)
#pragma unroll
        for (int j = 0; j < 4; j++) acc[i][j] = 0.f;

    for (int k0 = 0; k0 < K; k0 += 16) {
        float4 av = *(const float4*)(A + (long)(row0 + am) * lda + k0 + ak);
        *(float4*)&As[am][ak] = av;
        float4 bv = *(const float4*)(B + (long)(col0 + bn) * ldb + k0 + bk);
        Bs[bk + 0][bn] = bv.x; Bs[bk + 1][bn] = bv.y;
        Bs[bk + 2][bn] = bv.z; Bs[bk + 3][bn] = bv.w;
        __syncthreads();
#pragma unroll
        for (int kk = 0; kk < 16; kk++) {
            float a0 = As[tr * 4 + 0][kk];
            float a1 = As[tr * 4 + 1][kk];
            float a2 = As[tr * 4 + 2][kk];
            float a3 = As[tr * 4 + 3][kk];
            float b0 = Bs[kk][(tc << 2) + 0];
            float b1 = Bs[kk][(tc << 2) + 1];
            float b2 = Bs[kk][(tc << 2) + 2];
            float b3 = Bs[kk][(tc << 2) + 3];
            acc[0][0] += a0 * b0; acc[0][1] += a0 * b1; acc[0][2] += a0 * b2; acc[0][3] += a0 * b3;
            acc[1][0] += a1 * b0; acc[1][1] += a1 * b1; acc[1][2] += a1 * b2; acc[1][3] += a1 * b3;
            acc[2][0] += a2 * b0; acc[2][1] += a2 * b1; acc[2][2] += a2 * b2; acc[2][3] += a2 * b3;
            acc[3][0] += a3 * b0; acc[3][1] += a3 * b1; acc[3][2] += a3 * b2; acc[3][3] += a3 * b3;
        }
        __syncthreads();
    }

#pragma unroll
    for (int i = 0; i < 4; i++) {
        int r = row0 + tr * 4 + i;
        int qAbs = maskRowOff + r;
#pragma unroll
        for (int j = 0; j < 4; j++) {
            int c = col0 + (tc << 2) + j;
            float v = acc[i][j] * scale;
            if (causal && c > qAbs) v = -1e30f;
            C[(long)r * ldc + c] = v;
        }
    }
}

// ---------------- row softmax over 768 columns ------------------------------
__global__ void __launch_bounds__(256) softmax_rows(
    float* __restrict__ Sm, long zstride, int rowStart)
{
    float* row = Sm + (long)blockIdx.y * zstride + (long)(rowStart + blockIdx.x) * CL;
    int tid = threadIdx.x;
    __shared__ float red[256];

    float m = -1e30f;
    for (int c = tid; c < CL; c += 256) m = fmaxf(m, row[c]);
    red[tid] = m; __syncthreads();
    for (int s = 128; s > 0; s >>= 1) { if (tid < s) red[tid] = fmaxf(red[tid], red[tid + s]); __syncthreads(); }
    m = red[0]; __syncthreads();

    float sum = 0.f;
    for (int c = tid; c < CL; c += 256) { float e = __expf(row[c] - m); row[c] = e; sum += e; }
    red[tid] = sum; __syncthreads();
    for (int s = 128; s > 0; s >>= 1) { if (tid < s) red[tid] += red[tid + s]; __syncthreads(); }
    float inv = 1.f / red[0];
    for (int c = tid; c < CL; c += 256) row[c] *= inv;
}

// ---------------- small copy kernels ----------------------------------------
__global__ void bcast_state(const float* __restrict__ src, float* __restrict__ dst)
{
    int i = blockIdx.x * blockDim.x + threadIdx.x;
    if (i >= CSL * CD) return;
    dst[i] = src[i];
    dst[CSL * CD + i] = src[i];
}

__global__ void dup_tail(float* __restrict__ kk, float* __restrict__ qq, float* __restrict__ vv)
{
    int i = blockIdx.x * blockDim.x + threadIdx.x;
    if (i >= CBH * CSL * CDK) return;
    int c = i % CDK, r = (i / CDK) % CSL, z = i / (CDK * CSL);
    long src = ((long)z * CL + r) * CDK + c;
    long dst = ((long)z * CL + (CSL + CSEG) + r) * CDK + c;
    kk[dst] = kk[src]; qq[dst] = qq[src]; vv[dst] = vv[src];
}

__global__ void build_mid(const float* __restrict__ kf, const float* __restrict__ qf,
                          const float* __restrict__ vf,
                          float* __restrict__ kk, float* __restrict__ qq,
                          float* __restrict__ vv, int seg)
{
    int i = blockIdx.x * blockDim.x + threadIdx.x;
    if (i >= CBH * CSEG * CDK) return;
    int c = i % CDK, r = (i / CDK) % CSEG, z = i / (CDK * CSEG);
    long src = ((long)z * CS + seg * CSEG + r) * CDK + c;
    long dst = ((long)z * CL + CSL + r) * CDK + c;
    kk[dst] = kf[src]; qq[dst] = qf[src]; vv[dst] = vf[src];
}

// ---------------- host-side launch helpers ----------------------------------
static void nn(int M, int N, int K,
               const float* A, int lda, long sAb, long sAh,
               const float* B, int ldb, long sBb, long sBh,
               float* C, int ldc, long sC,
               float* C2, int ldc2, long sC2, int split,
               float scale, int Z, int nh)
{
    dim3 g(M / 64, N / 64, Z);
    sgemm_nn<<<g, 256>>>(K, A, lda, sAb, sAh, B, ldb, sBb, sBh,
                         C, ldc, sC, C2, ldc2, sC2, split, scale, nh);
}

static void nt(int M, int N, int K,
               const float* A, int lda, long sA,
               const float* B, int ldb, long sB,
               float* C, int ldc, long sC,
               float scale, int causal, int maskRowOff, int Z)
{
    dim3 g(M / 64, N / 64, Z);
    sgemm_nt<<<g, 256>>>(K, A, lda, sA, B, ldb, sB, C, ldc, sC,
                         scale, causal, maskRowOff);
}

static float* sym_addr(const void* s)
{
    void* t = nullptr;
    cudaGetSymbolAddress(&t, s);
    return (float*)t;
}

extern "C" void kernel_launch(void* const* d_in, const int* in_sizes, int n_in,
                              void* d_out, int out_size)
{
    const float* x     = (const float*)d_in[0];
    const float* st0   = (const float*)d_in[1];
    const float* Wk    = (const float*)d_in[2];
    const float* Wq    = (const float*)d_in[3];
    const float* Wv    = (const float*)d_in[4];
    const float* W2k   = (const float*)d_in[5];
    const float* Wout  = (const float*)d_in[6];
    const float* Wks   = (const float*)d_in[7];
    const float* Wqs   = (const float*)d_in[8];
    const float* Wvs   = (const float*)d_in[9];
    const float* W2kss = (const float*)d_in[10];
    const float* W2qss = (const float*)d_in[11];
    const float* W2vss = (const float*)d_in[12];
    const float* W2kse = (const float*)d_in[13];
    const float* W2qse = (const float*)d_in[14];
    const float* W2vse = (const float*)d_in[15];
    const float* Wos   = (const float*)d_in[16];
    float* out = (float*)d_out;

    static float *kf = nullptr, *qf, *vf, *stb, *kk, *qq, *vv, *s1, *att1, *k2, *q2, *v2, *a2c, *a2e;
    if (!kf) {
        kf = sym_addr(g_kf);   qf = sym_addr(g_qf);   vf = sym_addr(g_vf);
        stb = sym_addr(g_state); kk = sym_addr(g_kk); qq = sym_addr(g_qq);
        vv = sym_addr(g_vv);   s1 = sym_addr(g_s1);   att1 = sym_addr(g_att1);
        k2 = sym_addr(g_k2);   q2 = sym_addr(g_q2);   v2 = sym_addr(g_v2);
        a2c = sym_addr(g_a2c); a2e = sym_addr(g_a2e);
    }

    const int BIG = 1 << 30;
    const float SC = 0.125f;  // 1/sqrt(DK)

    // ---- full-sequence projections: kf/qf/vf = x @ W[h] ----
    nn(CS, CDK, CD, x, CD, (long)CS * CD, 0, Wk, CDK, 0, (long)CD * CDK,
       kf, CDK, (long)CS * CDK, nullptr, 0, 0, BIG, 1.f, CBH, CH);
    nn(CS, CDK, CD, x, CD, (long)CS * CD, 0, Wq, CDK, 0, (long)CD * CDK,
       qf, CDK, (long)CS * CDK, nullptr, 0, 0, BIG, 1.f, CBH, CH);
    nn(CS, CDV, CD, x, CD, (long)CS * CD, 0, Wv, CDV, 0, (long)CD * CDV,
       vf, CDV, (long)CS * CDV, nullptr, 0, 0, BIG, 1.f, CBH, CH);

    bcast_state<<<(CSL * CD + 255) / 256, 256>>>(st0, stb);

    for (int seg = 0; seg < 4; seg++) {
        // ---- state projections -> rows [0,128) of kk/qq/vv ----
        nn(CSL, CDK, CD, stb, CD, (long)CSL * CD, 0, Wks, CDK, 0, (long)CD * CDK,
           kk, CDK, (long)CL * CDK, nullptr, 0, 0, BIG, 1.f, CBH, CH);
        nn(CSL, CDK, CD, stb, CD, (long)CSL * CD, 0, Wqs, CDK, 0, (long)CD * CDK,
           qq, CDK, (long)CL * CDK, nullptr, 0, 0, BIG, 1.f, CBH, CH);
        nn(CSL, CDV, CD, stb, CD, (long)CSL * CD, 0, Wvs, CDV, 0, (long)CD * CDV,
           vv, CDV, (long)CL * CDV, nullptr, 0, 0, BIG, 1.f, CBH, CH);
        dup_tail<<<(CBH * CSL * CDK + 255) / 256, 256>>>(kk, qq, vv);
        build_mid<<<(CBH * CSEG * CDK + 255) / 256, 256>>>(kf, qf, vf, kk, qq, vv, seg);

        // ---- attention 1 (L=768, e=64, causal) ----
        nt(CL, CL, CDK, qq, CDK, (long)CL * CDK, kk, CDK, (long)CL * CDK,
           s1, CL, (long)CL * CL, SC, 1, 0, CBH);
        softmax_rows<<<dim3(CL, CBH), 256>>>(s1, (long)CL * CL, 0);
        nn(CL, CDV, CL, s1, CL, (long)CL * CL, 0, vv, CDV, (long)CL * CDV, 0,
           att1, CDV, (long)CL * CDV, nullptr, 0, 0, BIG, 1.f, CBH, 1);

        // ---- second projections: k2/q2/v2 [z][768][128] ----
        const float* WS[3] = { W2kss, W2qss, W2vss };
        const float* WE[3] = { W2kse, W2qse, W2vse };
        float* DST[3] = { k2, q2, v2 };
        for (int t = 0; t < 3; t++) {
            nn(CSL, C2DV, CDV, att1, CDV, (long)CH * CL * CDV, (long)CL * CDV,
               WS[t], C2DV, 0, (long)CDV * C2DV,
               DST[t], C2DV, (long)CL * C2DV, nullptr, 0, 0, BIG, 1.f, CBH, CH);
            // middle part uses W2k for k2, q2 AND v2 (matches reference)
            nn(CSEG, C2DV, CDV, att1 + (long)CSL * CDV, CDV, (long)CH * CL * CDV, (long)CL * CDV,
               W2k, C2DV, 0, (long)CDV * C2DV,
               DST[t] + (long)CSL * C2DV, C2DV, (long)CL * C2DV, nullptr, 0, 0, BIG, 1.f, CBH, CH);
            nn(CSL, C2DV, CDV, att1 + (long)(CSL + CSEG) * CDV, CDV, (long)CH * CL * CDV, (long)CL * CDV,
               WE[t], C2DV, 0, (long)CDV * C2DV,
               DST[t] + (long)(CSL + CSEG) * C2DV, C2DV, (long)CL * C2DV, nullptr, 0, 0, BIG, 1.f, CBH, CH);
        }

        // ---- attention 2 (queries 128..767 only; first 128 rows are unused) ----
        nt(CL - CSL, CL, C2DV, q2 + (long)CSL * C2DV, C2DV, (long)CL * C2DV,
           k2, C2DV, (long)CL * C2DV,
           s1 + (long)CSL * CL, CL, (long)CL * CL, SC, 1, CSL, CBH);
        softmax_rows<<<dim3(CL - CSL, CBH), 256>>>(s1, (long)CL * CL, CSL);
        // split store: local rows [0,512) -> a2c (mid), [512,640) -> a2e (end)
        nn(CL - CSL, C2DV, CL, s1 + (long)CSL * CL, CL, (long)CL * CL, 0,
           v2, C2DV, (long)CL * C2DV, 0,
           a2c, C2DV, (long)CSEG * C2DV,
           a2e, C2DV, (long)CSL * C2DV, CSEG, 1.f, CBH, 1);

        // ---- output GEMM: per-b [512 x 2048] @ Wout[2048 x 1024] ----
        nn(CSEG, CD, 2 * CH * CDV, a2c, 2 * CH * CDV, (long)CH * CSEG * C2DV, 0,
           Wout, CD, 0, 0,
           out + (long)seg * CSEG * CD, CD, (long)CS * CD,
           nullptr, 0, 0, BIG, 1.f, CB, 1);

        // ---- state GEMM: per-b [128 x 2048] @ Wout_state ----
        float* dst = (seg < 3) ? stb : (out + (long)CB * CS * CD);
        nn(CSL, CD, 2 * CH * CDV, a2e, 2 * CH * CDV, (long)CH * CSL * C2DV, 0,
           Wos, CD, 0, 0,
           dst, CD, (long)CSL * CD,
           nullptr, 0, 0, BIG, 1.f, CB, 1);
    }
}

// round 5
// speedup vs baseline: 1.5444x; 1.5444x over previous
#include <cuda_runtime.h>
#include <cuda_bf16.h>
#include <cstdint>

// ---------------- problem constants ----------------
#define CB   2
#define CS   2048
#define CD   1024
#define CH   16
#define CDK  64
#define CDV  64
#define CSEG 512
#define CSL  128
#define CL   768          // SL + SEG + SL
#define CBH  32           // B*H
#define C2DV 128          // 2*DV

// ---------------- scratch (device globals) ----------------------------------
__device__ float g_kf[CB*CH*CS*CDK];
__device__ float g_qf[CB*CH*CS*CDK];
__device__ float g_vf[CB*CH*CS*CDV];
__device__ float g_state[CB*CSL*CD];
__device__ float g_kk[CBH*CL*CDK];
__device__ float g_qq[CBH*CL*CDK];
__device__ float g_vv[CBH*CL*CDV];
__device__ float g_s1[CBH*CL*CL];
__device__ float g_att1[CBH*CL*CDV];
__device__ float g_k2[CBH*CL*C2DV];
__device__ float g_q2[CBH*CL*C2DV];
__device__ float g_v2[CBH*CL*C2DV];
__device__ float g_a2c[CB*CH*CSEG*C2DV];
__device__ float g_a2e[CB*CH*CSL*C2DV];
// transposed operands (NT form: B given as [N][K])
__device__ float g_WkT [CH*CDK*CD];
__device__ float g_WqT [CH*CDK*CD];
__device__ float g_WvT [CH*CDV*CD];
__device__ float g_WksT[CH*CDK*CD];
__device__ float g_WqsT[CH*CDK*CD];
__device__ float g_WvsT[CH*CDV*CD];
__device__ float g_W2kT  [CH*C2DV*CDV];
__device__ float g_W2kssT[CH*C2DV*CDV];
__device__ float g_W2qssT[CH*C2DV*CDV];
__device__ float g_W2vssT[CH*C2DV*CDV];
__device__ float g_W2kseT[CH*C2DV*CDV];
__device__ float g_W2qseT[CH*C2DV*CDV];
__device__ float g_W2vseT[CH*C2DV*CDV];
__device__ float g_WoutT[CD*2*CH*CDV];
__device__ float g_WosT [CD*2*CH*CDV];
__device__ float g_vvT[CBH*CDV*CL];
__device__ float g_v2T[CBH*C2DV*CL];

// ---------------- helpers ----------------------------------------------------
__device__ __forceinline__ uint32_t smem_u32(const void* p) {
    uint32_t a;
    asm("{ .reg .u64 t; cvta.to.shared.u64 t, %1; cvt.u32.u64 %0, t; }" : "=r"(a) : "l"(p));
    return a;
}

__device__ __forceinline__ void ldm_x4(uint32_t* r, uint32_t addr) {
    asm volatile("ldmatrix.sync.aligned.m8n8.x4.shared.b16 {%0,%1,%2,%3}, [%4];"
                 : "=r"(r[0]), "=r"(r[1]), "=r"(r[2]), "=r"(r[3]) : "r"(addr));
}
__device__ __forceinline__ void ldm_x2(uint32_t* r, uint32_t addr) {
    asm volatile("ldmatrix.sync.aligned.m8n8.x2.shared.b16 {%0,%1}, [%2];"
                 : "=r"(r[0]), "=r"(r[1]) : "r"(addr));
}
__device__ __forceinline__ void mma_bf16(float* d, const uint32_t* a, const uint32_t* b) {
    asm volatile("mma.sync.aligned.m16n8k16.row.col.f32.bf16.bf16.f32 "
                 "{%0,%1,%2,%3}, {%4,%5,%6,%7}, {%8,%9}, {%0,%1,%2,%3};"
                 : "+f"(d[0]), "+f"(d[1]), "+f"(d[2]), "+f"(d[3])
                 : "r"(a[0]), "r"(a[1]), "r"(a[2]), "r"(a[3]), "r"(b[0]), "r"(b[1]));
}

__device__ __forceinline__ void split2(float x, float y, uint32_t& hi, uint32_t& lo) {
    __nv_bfloat16 hx = __float2bfloat16_rn(x), hy = __float2bfloat16_rn(y);
    __nv_bfloat16 lx = __float2bfloat16_rn(x - __bfloat162float(hx));
    __nv_bfloat16 ly = __float2bfloat16_rn(y - __bfloat162float(hy));
    hi = ((uint32_t)__bfloat16_as_ushort(hy) << 16) | __bfloat16_as_ushort(hx);
    lo = ((uint32_t)__bfloat16_as_ushort(ly) << 16) | __bfloat16_as_ushort(lx);
}

// ---------------- tensor-core (HMMA) NT GEMM --------------------------------
// C[M,N] = scale * A[M,K] @ B[N,K]^T   (fp32 in/out; bf16 hi/lo, 3 MMAs)
// CTA tile 128x64, 8 warps of 32x32, K-chunk 32. grid=(M/128, N/64, Z)
// batching: b=z/nh, h=z%nh. split-store + optional causal mask in epilogue.
#define LDS 40   // bf16 row stride of smem tiles (pad 32->40 to kill conflicts)

__global__ void __launch_bounds__(256) mma_gemm_nt(
    int K,
    const float* __restrict__ A, int lda, long sAb, long sAh,
    const float* __restrict__ B, int ldb, long sBb, long sBh,
    float* __restrict__ C, int ldc, long sC,
    float* __restrict__ C2, int ldc2, long sC2, int splitRow,
    float scale, int causal, int maskRowOff, int nh)
{
    __shared__ __nv_bfloat16 sAh_[128 * LDS], sAl_[128 * LDS];
    __shared__ __nv_bfloat16 sBh_[64 * LDS],  sBl_[64 * LDS];

    int z = blockIdx.z, b = z / nh, h = z - b * nh;
    A += (long)b * sAb + (long)h * sAh;
    B += (long)b * sBb + (long)h * sBh;
    C += (long)z * sC;
    if (C2) C2 += (long)z * sC2;

    int tid = threadIdx.x;
    int lane = tid & 31, w = tid >> 5;
    int wm = w & 3, wn = w >> 2;                 // warp tile: rows wm*32, cols wn*32
    int row0 = blockIdx.x * 128, col0 = blockIdx.y * 64;

    uint32_t baseAh = smem_u32(sAh_), baseAl = smem_u32(sAl_);
    uint32_t baseBh = smem_u32(sBh_), baseBl = smem_u32(sBl_);

    // ldmatrix per-lane source offsets (bytes)
    uint32_t aOff = (uint32_t)((wm * 32 + (lane & 15)) * LDS * 2 + (lane >> 4) * 16);
    uint32_t bOffBase = (uint32_t)((wn * 32 + (lane & 7)) * LDS * 2 + ((lane >> 3) & 1) * 16);

    float acc[2][4][4];
#pragma unroll
    for (int mi = 0; mi < 2; mi++)
#pragma unroll
        for (int nj = 0; nj < 4; nj++)
#pragma unroll
            for (int q = 0; q < 4; q++) acc[mi][nj][q] = 0.f;

    int nchunk = K >> 5;
    for (int ch = 0; ch < nchunk; ch++) {
        int k0 = ch << 5;
        // ---- A tile 128x32 fp32 -> bf16 hi/lo smem ----
#pragma unroll
        for (int i = 0; i < 4; i++) {
            int idx = tid + (i << 8);
            int r = idx >> 3, c4 = (idx & 7) << 2;
            float4 v = *(const float4*)(A + (long)(row0 + r) * lda + k0 + c4);
            uint32_t h01, l01, h23, l23;
            split2(v.x, v.y, h01, l01);
            split2(v.z, v.w, h23, l23);
            *(uint2*)&sAh_[r * LDS + c4] = make_uint2(h01, h23);
            *(uint2*)&sAl_[r * LDS + c4] = make_uint2(l01, l23);
        }
        // ---- B tile 64x32 fp32 -> bf16 hi/lo smem ----
#pragma unroll
        for (int i = 0; i < 2; i++) {
            int idx = tid + (i << 8);
            int r = idx >> 3, c4 = (idx & 7) << 2;
            float4 v = *(const float4*)(B + (long)(col0 + r) * ldb + k0 + c4);
            uint32_t h01, l01, h23, l23;
            split2(v.x, v.y, h01, l01);
            split2(v.z, v.w, h23, l23);
            *(uint2*)&sBh_[r * LDS + c4] = make_uint2(h01, h23);
            *(uint2*)&sBl_[r * LDS + c4] = make_uint2(l01, l23);
        }
        __syncthreads();

#pragma unroll
        for (int kb = 0; kb < 2; kb++) {
            uint32_t aH[2][4], aL[2][4], bH[4][2], bL[4][2];
#pragma unroll
            for (int mi = 0; mi < 2; mi++) {
                uint32_t off = aOff + (uint32_t)(mi * 16 * LDS * 2 + kb * 32);
                ldm_x4(aH[mi], baseAh + off);
                ldm_x4(aL[mi], baseAl + off);
            }
#pragma unroll
            for (int nj = 0; nj < 4; nj++) {
                uint32_t off = bOffBase + (uint32_t)(nj * 8 * LDS * 2 + kb * 32);
                ldm_x2(bH[nj], baseBh + off);
                ldm_x2(bL[nj], baseBl + off);
            }
#pragma unroll
            for (int mi = 0; mi < 2; mi++)
#pragma unroll
                for (int nj = 0; nj < 4; nj++) {
                    mma_bf16(acc[mi][nj], aH[mi], bH[nj]);
                    mma_bf16(acc[mi][nj], aH[mi], bL[nj]);
                    mma_bf16(acc[mi][nj], aL[mi], bH[nj]);
                }
        }
        __syncthreads();
    }

    // ---- epilogue: scale, causal mask, split store ----
    int rb = row0 + wm * 32 + (lane >> 2);
    int cb = col0 + wn * 32 + ((lane & 3) << 1);
#pragma unroll
    for (int mi = 0; mi < 2; mi++) {
#pragma unroll
        for (int half = 0; half < 2; half++) {
            int r = rb + mi * 16 + half * 8;
            int qAbs = maskRowOff + r;
            float* dst;
            int rr, ld;
            if (r < splitRow) { dst = C;  rr = r;            ld = ldc;  }
            else              { dst = C2; rr = r - splitRow; ld = ldc2; }
#pragma unroll
            for (int nj = 0; nj < 4; nj++) {
                int c = cb + nj * 8;
                float2 v;
                v.x = acc[mi][nj][half * 2 + 0] * scale;
                v.y = acc[mi][nj][half * 2 + 1] * scale;
                if (causal) {
                    if (c + 0 > qAbs) v.x = -1e30f;
                    if (c + 1 > qAbs) v.y = -1e30f;
                }
                *(float2*)(dst + (long)rr * ld + c) = v;
            }
        }
    }
}

// ---------------- tiled transpose: out[z][c][r] = in[z][r][c] ----------------
__global__ void transpose_k(const float* __restrict__ in, float* __restrict__ out,
                            int R, int Ccols, long sIn, long sOut)
{
    __shared__ float t[32][33];
    int z = blockIdx.z;
    in += (long)z * sIn; out += (long)z * sOut;
    int r0 = blockIdx.x * 32, c0 = blockIdx.y * 32;
    int x = threadIdx.x, y = threadIdx.y;
    for (int i = y; i < 32; i += 8)
        t[i][x] = in[(long)(r0 + i) * Ccols + c0 + x];
    __syncthreads();
    for (int i = y; i < 32; i += 8)
        out[(long)(c0 + i) * R + r0 + x] = t[x][i];
}

// ---------------- row softmax over 768 columns ------------------------------
__global__ void __launch_bounds__(256) softmax_rows(
    float* __restrict__ Sm, long zstride, int rowStart)
{
    float* row = Sm + (long)blockIdx.y * zstride + (long)(rowStart + blockIdx.x) * CL;
    int tid = threadIdx.x;
    __shared__ float red[256];

    float m = -1e30f;
    for (int c = tid; c < CL; c += 256) m = fmaxf(m, row[c]);
    red[tid] = m; __syncthreads();
    for (int s = 128; s > 0; s >>= 1) { if (tid < s) red[tid] = fmaxf(red[tid], red[tid + s]); __syncthreads(); }
    m = red[0]; __syncthreads();

    float sum = 0.f;
    for (int c = tid; c < CL; c += 256) { float e = __expf(row[c] - m); row[c] = e; sum += e; }
    red[tid] = sum; __syncthreads();
    for (int s = 128; s > 0; s >>= 1) { if (tid < s) red[tid] += red[tid + s]; __syncthreads(); }
    float inv = 1.f / red[0];
    for (int c = tid; c < CL; c += 256) row[c] *= inv;
}

// ---------------- small copy kernels ----------------------------------------
__global__ void bcast_state(const float* __restrict__ src, float* __restrict__ dst)
{
    int i = blockIdx.x * blockDim.x + threadIdx.x;
    if (i >= CSL * CD) return;
    dst[i] = src[i];
    dst[CSL * CD + i] = src[i];
}

__global__ void dup_tail(float* __restrict__ kk, float* __restrict__ qq, float* __restrict__ vv)
{
    int i = blockIdx.x * blockDim.x + threadIdx.x;
    if (i >= CBH * CSL * CDK) return;
    int c = i % CDK, r = (i / CDK) % CSL, z = i / (CDK * CSL);
    long src = ((long)z * CL + r) * CDK + c;
    long dst = ((long)z * CL + (CSL + CSEG) + r) * CDK + c;
    kk[dst] = kk[src]; qq[dst] = qq[src]; vv[dst] = vv[src];
}

__global__ void build_mid(const float* __restrict__ kf, const float* __restrict__ qf,
                          const float* __restrict__ vf,
                          float* __restrict__ kk, float* __restrict__ qq,
                          float* __restrict__ vv, int seg)
{
    int i = blockIdx.x * blockDim.x + threadIdx.x;
    if (i >= CBH * CSEG * CDK) return;
    int c = i % CDK, r = (i / CDK) % CSEG, z = i / (CDK * CSEG);
    long src = ((long)z * CS + seg * CSEG + r) * CDK + c;
    long dst = ((long)z * CL + CSL + r) * CDK + c;
    kk[dst] = kf[src]; qq[dst] = qf[src]; vv[dst] = vf[src];
}

__global__ void dup_mid(const float* __restrict__ k2,
                        float* __restrict__ q2, float* __restrict__ v2)
{
    int i = blockIdx.x * blockDim.x + threadIdx.x;
    if (i >= CBH * CSEG * C2DV) return;
    int c = i % (CSEG * C2DV);
    int z = i / (CSEG * C2DV);
    long off = ((long)z * CL + CSL) * C2DV + c;
    float v = k2[off];
    q2[off] = v; v2[off] = v;
}

// ---------------- host helpers ----------------------------------------------
static void tc(int M, int N, int K,
               const float* A, int lda, long sAb, long sAh,
               const float* B, int ldb, long sBb, long sBh,
               float* C, int ldc, long sC,
               float* C2, int ldc2, long sC2, int split,
               float scale, int causal, int maskRowOff, int Z, int nh)
{
    dim3 g(M / 128, N / 64, Z);
    mma_gemm_nt<<<g, 256>>>(K, A, lda, sAb, sAh, B, ldb, sBb, sBh,
                            C, ldc, sC, C2, ldc2, sC2, split,
                            scale, causal, maskRowOff, nh);
}

static void tr(const float* in, float* out, int R, int C, long sIn, long sOut, int Z)
{
    dim3 g(R / 32, C / 32, Z);
    transpose_k<<<g, dim3(32, 8)>>>(in, out, R, C, sIn, sOut);
}

static float* sym_addr(const void* s)
{
    void* t = nullptr;
    cudaGetSymbolAddress(&t, s);
    return (float*)t;
}

extern "C" void kernel_launch(void* const* d_in, const int* in_sizes, int n_in,
                              void* d_out, int out_size)
{
    const float* x     = (const float*)d_in[0];
    const float* st0   = (const float*)d_in[1];
    const float* Wk    = (const float*)d_in[2];
    const float* Wq    = (const float*)d_in[3];
    const float* Wv    = (const float*)d_in[4];
    const float* W2k   = (const float*)d_in[5];
    const float* Wout  = (const float*)d_in[6];
    const float* Wks   = (const float*)d_in[7];
    const float* Wqs   = (const float*)d_in[8];
    const float* Wvs   = (const float*)d_in[9];
    const float* W2kss = (const float*)d_in[10];
    const float* W2qss = (const float*)d_in[11];
    const float* W2vss = (const float*)d_in[12];
    const float* W2kse = (const float*)d_in[13];
    const float* W2qse = (const float*)d_in[14];
    const float* W2vse = (const float*)d_in[15];
    const float* Wos   = (const float*)d_in[16];
    float* out = (float*)d_out;

    static float *kf = nullptr, *qf, *vf, *stb, *kk, *qq, *vv, *s1, *att1, *k2, *q2, *v2, *a2c, *a2e;
    static float *WkT, *WqT, *WvT, *WksT, *WqsT, *WvsT;
    static float *W2kT, *W2kssT, *W2qssT, *W2vssT, *W2kseT, *W2qseT, *W2vseT;
    static float *WoutT, *WosT, *vvT, *v2T;
    if (!kf) {
        kf = sym_addr(g_kf);   qf = sym_addr(g_qf);   vf = sym_addr(g_vf);
        stb = sym_addr(g_state); kk = sym_addr(g_kk); qq = sym_addr(g_qq);
        vv = sym_addr(g_vv);   s1 = sym_addr(g_s1);   att1 = sym_addr(g_att1);
        k2 = sym_addr(g_k2);   q2 = sym_addr(g_q2);   v2 = sym_addr(g_v2);
        a2c = sym_addr(g_a2c); a2e = sym_addr(g_a2e);
        WkT = sym_addr(g_WkT); WqT = sym_addr(g_WqT); WvT = sym_addr(g_WvT);
        WksT = sym_addr(g_WksT); WqsT = sym_addr(g_WqsT); WvsT = sym_addr(g_WvsT);
        W2kT = sym_addr(g_W2kT); W2kssT = sym_addr(g_W2kssT); W2qssT = sym_addr(g_W2qssT);
        W2vssT = sym_addr(g_W2vssT); W2kseT = sym_addr(g_W2kseT); W2qseT = sym_addr(g_W2qseT);
        W2vseT = sym_addr(g_W2vseT); WoutT = sym_addr(g_WoutT); WosT = sym_addr(g_WosT);
        vvT = sym_addr(g_vvT); v2T = sym_addr(g_v2T);
    }

    const int BIG = 1 << 30;
    const float SC = 0.125f;
    const long WH = (long)CD * CDK;
    const long W2H = (long)CDV * C2DV;

    // ---- transpose all weights into NT form ----
    tr(Wk,  WkT,  CD, CDK, WH, WH, CH);
    tr(Wq,  WqT,  CD, CDK, WH, WH, CH);
    tr(Wv,  WvT,  CD, CDV, WH, WH, CH);
    tr(Wks, WksT, CD, CDK, WH, WH, CH);
    tr(Wqs, WqsT, CD, CDK, WH, WH, CH);
    tr(Wvs, WvsT, CD, CDV, WH, WH, CH);
    tr(W2k,   W2kT,   CDV, C2DV, W2H, W2H, CH);
    tr(W2kss, W2kssT, CDV, C2DV, W2H, W2H, CH);
    tr(W2qss, W2qssT, CDV, C2DV, W2H, W2H, CH);
    tr(W2vss, W2vssT, CDV, C2DV, W2H, W2H, CH);
    tr(W2kse, W2kseT, CDV, C2DV, W2H, W2H, CH);
    tr(W2qse, W2qseT, CDV, C2DV, W2H, W2H, CH);
    tr(W2vse, W2vseT, CDV, C2DV, W2H, W2H, CH);
    tr(Wout, WoutT, 2 * CH * CDV, CD, 0, 0, 1);
    tr(Wos,  WosT,  2 * CH * CDV, CD, 0, 0, 1);

    // ---- full-sequence projections ----
    tc(CS, CDK, CD, x, CD, (long)CS * CD, 0, WkT, CD, 0, WH,
       kf, CDK, (long)CS * CDK, nullptr, 0, 0, BIG, 1.f, 0, 0, CBH, CH);
    tc(CS, CDK, CD, x, CD, (long)CS * CD, 0, WqT, CD, 0, WH,
       qf, CDK, (long)CS * CDK, nullptr, 0, 0, BIG, 1.f, 0, 0, CBH, CH);
    tc(CS, CDV, CD, x, CD, (long)CS * CD, 0, WvT, CD, 0, WH,
       vf, CDV, (long)CS * CDV, nullptr, 0, 0, BIG, 1.f, 0, 0, CBH, CH);

    bcast_state<<<(CSL * CD + 255) / 256, 256>>>(st0, stb);

    for (int seg = 0; seg < 4; seg++) {
        // ---- state projections -> rows [0,128) ----
        tc(CSL, CDK, CD, stb, CD, (long)CSL * CD, 0, WksT, CD, 0, WH,
           kk, CDK, (long)CL * CDK, nullptr, 0, 0, BIG, 1.f, 0, 0, CBH, CH);
        tc(CSL, CDK, CD, stb, CD, (long)CSL * CD, 0, WqsT, CD, 0, WH,
           qq, CDK, (long)CL * CDK, nullptr, 0, 0, BIG, 1.f, 0, 0, CBH, CH);
        tc(CSL, CDV, CD, stb, CD, (long)CSL * CD, 0, WvsT, CD, 0, WH,
           vv, CDV, (long)CL * CDV, nullptr, 0, 0, BIG, 1.f, 0, 0, CBH, CH);
        dup_tail<<<(CBH * CSL * CDK + 255) / 256, 256>>>(kk, qq, vv);
        build_mid<<<(CBH * CSEG * CDK + 255) / 256, 256>>>(kf, qf, vf, kk, qq, vv, seg);

        // ---- attention 1 ----
        tc(CL, CL, CDK, qq, CDK, (long)CL * CDK, 0, kk, CDK, (long)CL * CDK, 0,
           s1, CL, (long)CL * CL, nullptr, 0, 0, BIG, SC, 1, 0, CBH, 1);
        softmax_rows<<<dim3(CL, CBH), 256>>>(s1, (long)CL * CL, 0);
        tr(vv, vvT, CL, CDV, (long)CL * CDV, (long)CDV * CL, CBH);
        tc(CL, CDV, CL, s1, CL, (long)CL * CL, 0, vvT, CL, (long)CDV * CL, 0,
           att1, CDV, (long)CL * CDV, nullptr, 0, 0, BIG, 1.f, 0, 0, CBH, 1);

        // ---- second projections ----
        const long sA1b = (long)CH * CL * CDV, sA1h = (long)CL * CDV;
        tc(CSL, C2DV, CDV, att1, CDV, sA1b, sA1h, W2kssT, CDV, 0, W2H,
           k2, C2DV, (long)CL * C2DV, nullptr, 0, 0, BIG, 1.f, 0, 0, CBH, CH);
        tc(CSL, C2DV, CDV, att1, CDV, sA1b, sA1h, W2qssT, CDV, 0, W2H,
           q2, C2DV, (long)CL * C2DV, nullptr, 0, 0, BIG, 1.f, 0, 0, CBH, CH);
        tc(CSL, C2DV, CDV, att1, CDV, sA1b, sA1h, W2vssT, CDV, 0, W2H,
           v2, C2DV, (long)CL * C2DV, nullptr, 0, 0, BIG, 1.f, 0, 0, CBH, CH);
        // mid (k2/q2/v2 all use W2k per reference) — compute once, duplicate
        tc(CSEG, C2DV, CDV, att1 + (long)CSL * CDV, CDV, sA1b, sA1h, W2kT, CDV, 0, W2H,
           k2 + (long)CSL * C2DV, C2DV, (long)CL * C2DV, nullptr, 0, 0, BIG, 1.f, 0, 0, CBH, CH);
        dup_mid<<<(CBH * CSEG * C2DV + 255) / 256, 256>>>(k2, q2, v2);
        tc(CSL, C2DV, CDV, att1 + (long)(CSL + CSEG) * CDV, CDV, sA1b, sA1h, W2kseT, CDV, 0, W2H,
           k2 + (long)(CSL + CSEG) * C2DV, C2DV, (long)CL * C2DV, nullptr, 0, 0, BIG, 1.f, 0, 0, CBH, CH);
        tc(CSL, C2DV, CDV, att1 + (long)(CSL + CSEG) * CDV, CDV, sA1b, sA1h, W2qseT, CDV, 0, W2H,
           q2 + (long)(CSL + CSEG) * C2DV, C2DV, (long)CL * C2DV, nullptr, 0, 0, BIG, 1.f, 0, 0, CBH, CH);
        tc(CSL, C2DV, CDV, att1 + (long)(CSL + CSEG) * CDV, CDV, sA1b, sA1h, W2vseT, CDV, 0, W2H,
           v2 + (long)(CSL + CSEG) * C2DV, C2DV, (long)CL * C2DV, nullptr, 0, 0, BIG, 1.f, 0, 0, CBH, CH);

        // ---- attention 2 (queries 128..767; first 128 rows unused) ----
        tc(CL - CSL, CL, C2DV, q2 + (long)CSL * C2DV, C2DV, (long)CL * C2DV, 0,
           k2, C2DV, (long)CL * C2DV, 0,
           s1 + (long)CSL * CL, CL, (long)CL * CL, nullptr, 0, 0, BIG, SC, 1, CSL, CBH, 1);
        softmax_rows<<<dim3(CL - CSL, CBH), 256>>>(s1, (long)CL * CL, CSL);
        tr(v2, v2T, CL, C2DV, (long)CL * C2DV, (long)C2DV * CL, CBH);
        tc(CL - CSL, C2DV, CL, s1 + (long)CSL * CL, CL, (long)CL * CL, 0,
           v2T, CL, (long)C2DV * CL, 0,
           a2c, C2DV, (long)CSEG * C2DV,
           a2e, C2DV, (long)CSL * C2DV, CSEG, 1.f, 0, 0, CBH, 1);

        // ---- output GEMMs ----
        tc(CSEG, CD, 2 * CH * CDV, a2c, 2 * CH * CDV, (long)CH * CSEG * C2DV, 0,
           WoutT, 2 * CH * CDV, 0, 0,
           out + (long)seg * CSEG * CD, CD, (long)CS * CD,
           nullptr, 0, 0, BIG, 1.f, 0, 0, CB, 1);

        float* dst = (seg < 3) ? stb : (out + (long)CB * CS * CD);
        tc(CSL, CD, 2 * CH * CDV, a2e, 2 * CH * CDV, (long)CH * CSL * C2DV, 0,
           WosT, 2 * CH * CDV, 0, 0,
           dst, CD, (long)CSL * CD,
           nullptr, 0, 0, BIG, 1.f, 0, 0, CB, 1);
    }
}

// round 8
// speedup vs baseline: 1.8952x; 1.2271x over previous
#include <cuda_runtime.h>
#include <cuda_bf16.h>
#include <cstdint>

// ---------------- problem constants ----------------
#define CB   2
#define CS   2048
#define CD   1024
#define CH   16
#define CDK  64
#define CDV  64
#define CSEG 512
#define CSL  128
#define CL   768          // SL + SEG + SL
#define CBH  32           // B*H
#define C2DV 128          // 2*DV

// ---------------- scratch (device globals) ----------------------------------
__device__ float g_kf[CB*CH*CS*CDK];
__device__ float g_qf[CB*CH*CS*CDK];
__device__ float g_vf[CB*CH*CS*CDV];
__device__ float g_state[CB*CSL*CD];
__device__ float g_kk[CBH*CL*CDK];
__device__ float g_qq[CBH*CL*CDK];
__device__ float g_vv[CBH*CL*CDV];
__device__ float g_s1[CBH*CL*CL];
__device__ float g_att1[CBH*CL*CDV];
__device__ float g_k2[CBH*CL*C2DV];
__device__ float g_q2[CBH*CL*C2DV];
__device__ float g_v2[CBH*CL*C2DV];
__device__ float g_a2c[CB*CH*CSEG*C2DV];
__device__ float g_a2e[CB*CH*CSL*C2DV];

// ---------------- helpers ----------------------------------------------------
__device__ __forceinline__ uint32_t smem_u32(const void* p) {
    uint32_t a;
    asm("{ .reg .u64 t; cvta.to.shared.u64 t, %1; cvt.u32.u64 %0, t; }" : "=r"(a) : "l"(p));
    return a;
}
__device__ __forceinline__ void ldm_x4(uint32_t* r, uint32_t addr) {
    asm volatile("ldmatrix.sync.aligned.m8n8.x4.shared.b16 {%0,%1,%2,%3}, [%4];"
                 : "=r"(r[0]), "=r"(r[1]), "=r"(r[2]), "=r"(r[3]) : "r"(addr));
}
__device__ __forceinline__ void ldm_x2(uint32_t* r, uint32_t addr) {
    asm volatile("ldmatrix.sync.aligned.m8n8.x2.shared.b16 {%0,%1}, [%2];"
                 : "=r"(r[0]), "=r"(r[1]) : "r"(addr));
}
__device__ __forceinline__ void mma_bf16(float* d, const uint32_t* a, const uint32_t* b) {
    asm volatile("mma.sync.aligned.m16n8k16.row.col.f32.bf16.bf16.f32 "
                 "{%0,%1,%2,%3}, {%4,%5,%6,%7}, {%8,%9}, {%0,%1,%2,%3};"
                 : "+f"(d[0]), "+f"(d[1]), "+f"(d[2]), "+f"(d[3])
                 : "r"(a[0]), "r"(a[1]), "r"(a[2]), "r"(a[3]), "r"(b[0]), "r"(b[1]));
}
__device__ __forceinline__ void split2(float x, float y, uint32_t& hi, uint32_t& lo) {
    __nv_bfloat16 hx = __float2bfloat16_rn(x), hy = __float2bfloat16_rn(y);
    __nv_bfloat16 lx = __float2bfloat16_rn(x - __bfloat162float(hx));
    __nv_bfloat16 ly = __float2bfloat16_rn(y - __bfloat162float(hy));
    hi = ((uint32_t)__bfloat16_as_ushort(hy) << 16) | __bfloat16_as_ushort(hx);
    lo = ((uint32_t)__bfloat16_as_ushort(ly) << 16) | __bfloat16_as_ushort(lx);
}

// ---------------- unified tensor-core GEMM -----------------------------------
// C = scale * A[M,K] @ B^T (B stored [N][K] if !transB, [K][N] if transB)
// fp32 in/out; bf16 hi/lo split, 3 MMAs. CTA tile 128x64, K-chunk 32, prefetch.
// grouping: blockIdx.z = g*zPer + z ; g selects (B0/B1/B2, C0/C1/C2).
// batching within group: b = z/nh, h = z%nh.
// dupC: store result to C0,C1,C2 (all groups=1).
// causal: mask col>maskRowOff+row; fully-masked tiles short-circuit.
// trimK: K loop ends at maskRowOff+row0+128 (exact for prob@V GEMMs).
// split: local row >= splitRow goes to D2 at (row-splitRow).
#define LDS 40

__global__ void __launch_bounds__(256) mma_gemm(
    int K,
    const float* __restrict__ A, int lda, long sAb, long sAh,
    const float* __restrict__ B0, const float* __restrict__ B1, const float* __restrict__ B2,
    int ldb, long sBb, long sBh, int transB,
    float* __restrict__ C0, float* __restrict__ C1, float* __restrict__ C2c,
    int ldc, long sC,
    float* __restrict__ D2, int ldd2, long sD2, int splitRow,
    float scale, int causal, int maskRowOff, int trimK, int dupC,
    int nh, int zPer)
{
    __shared__ __nv_bfloat16 sAh_[128 * LDS], sAl_[128 * LDS];
    __shared__ __nv_bfloat16 sBh_[64 * LDS],  sBl_[64 * LDS];

    int zz = blockIdx.z;
    int g = zz / zPer, z = zz - g * zPer;
    int b = z / nh, h = z - b * nh;

    const float* B = (g == 0) ? B0 : ((g == 1) ? B1 : B2);
    A += (long)b * sAb + (long)h * sAh;
    B += (long)b * sBb + (long)h * sBh;

    float *Cd0, *Cd1 = nullptr, *Cd2 = nullptr;
    if (dupC) {
        Cd0 = C0 + (long)z * sC; Cd1 = C1 + (long)z * sC; Cd2 = C2c + (long)z * sC;
    } else {
        float* Cs = (g == 0) ? C0 : ((g == 1) ? C1 : C2c);
        Cd0 = Cs + (long)z * sC;
    }
    if (D2) D2 += (long)z * sD2;

    int tid = threadIdx.x;
    int lane = tid & 31, w = tid >> 5;
    int wm = w & 3, wn = w >> 2;
    int row0 = blockIdx.x * 128, col0 = blockIdx.y * 64;

    // ---- fully-masked causal tile: fill and exit ----
    if (causal && col0 > maskRowOff + row0 + 127) {
#pragma unroll
        for (int i = 0; i < 8; i++) {
            int idx = tid + (i << 8);
            int r = idx >> 4, c4 = (idx & 15) << 2;
            float4 v = make_float4(-1e30f, -1e30f, -1e30f, -1e30f);
            *(float4*)(Cd0 + (long)(row0 + r) * ldc + col0 + c4) = v;
        }
        return;
    }

    int kEnd = K;
    if (trimK) { int lim = maskRowOff + row0 + 128; kEnd = lim < K ? lim : K; }
    int nchunk = kEnd >> 5;

    uint32_t baseAh = smem_u32(sAh_), baseAl = smem_u32(sAl_);
    uint32_t baseBh = smem_u32(sBh_), baseBl = smem_u32(sBl_);
    uint32_t aOff = (uint32_t)((wm * 32 + (lane & 15)) * LDS * 2 + (lane >> 4) * 16);
    uint32_t bOffBase = (uint32_t)((wn * 32 + (lane & 7)) * LDS * 2 + ((lane >> 3) & 1) * 16);

    float acc[2][4][4];
#pragma unroll
    for (int mi = 0; mi < 2; mi++)
#pragma unroll
        for (int nj = 0; nj < 4; nj++)
#pragma unroll
            for (int q = 0; q < 4; q++) acc[mi][nj][q] = 0.f;

    float4 pa[4], pb[2];
    // prefetch chunk 0
    {
        int k0 = 0;
#pragma unroll
        for (int i = 0; i < 4; i++) {
            int idx = tid + (i << 8);
            int r = idx >> 3, c4 = (idx & 7) << 2;
            pa[i] = *(const float4*)(A + (long)(row0 + r) * lda + k0 + c4);
        }
        if (transB) {
#pragma unroll
            for (int i = 0; i < 2; i++) {
                int idx = tid + (i << 8);
                int kr = idx >> 4, c4 = (idx & 15) << 2;
                pb[i] = *(const float4*)(B + (long)(k0 + kr) * ldb + col0 + c4);
            }
        } else {
#pragma unroll
            for (int i = 0; i < 2; i++) {
                int idx = tid + (i << 8);
                int r = idx >> 3, c4 = (idx & 7) << 2;
                pb[i] = *(const float4*)(B + (long)(col0 + r) * ldb + k0 + c4);
            }
        }
    }

    for (int ch = 0; ch < nchunk; ch++) {
        // ---- store prefetched regs to smem (convert + split) ----
#pragma unroll
        for (int i = 0; i < 4; i++) {
            int idx = tid + (i << 8);
            int r = idx >> 3, c4 = (idx & 7) << 2;
            uint32_t h01, l01, h23, l23;
            split2(pa[i].x, pa[i].y, h01, l01);
            split2(pa[i].z, pa[i].w, h23, l23);
            *(uint2*)&sAh_[r * LDS + c4] = make_uint2(h01, h23);
            *(uint2*)&sAl_[r * LDS + c4] = make_uint2(l01, l23);
        }
        if (transB) {
#pragma unroll
            for (int i = 0; i < 2; i++) {
                int idx = tid + (i << 8);
                int kr = idx >> 4, c4 = (idx & 15) << 2;
                float vv4[4] = { pb[i].x, pb[i].y, pb[i].z, pb[i].w };
#pragma unroll
                for (int j = 0; j < 4; j++) {
                    __nv_bfloat16 hh = __float2bfloat16_rn(vv4[j]);
                    __nv_bfloat16 ll = __float2bfloat16_rn(vv4[j] - __bfloat162float(hh));
                    sBh_[(c4 + j) * LDS + kr] = hh;
                    sBl_[(c4 + j) * LDS + kr] = ll;
                }
            }
        } else {
#pragma unroll
            for (int i = 0; i < 2; i++) {
                int idx = tid + (i << 8);
                int r = idx >> 3, c4 = (idx & 7) << 2;
                uint32_t h01, l01, h23, l23;
                split2(pb[i].x, pb[i].y, h01, l01);
                split2(pb[i].z, pb[i].w, h23, l23);
                *(uint2*)&sBh_[r * LDS + c4] = make_uint2(h01, h23);
                *(uint2*)&sBl_[r * LDS + c4] = make_uint2(l01, l23);
            }
        }
        // ---- prefetch next chunk into regs ----
        if (ch + 1 < nchunk) {
            int k0 = (ch + 1) << 5;
#pragma unroll
            for (int i = 0; i < 4; i++) {
                int idx = tid + (i << 8);
                int r = idx >> 3, c4 = (idx & 7) << 2;
                pa[i] = *(const float4*)(A + (long)(row0 + r) * lda + k0 + c4);
            }
            if (transB) {
#pragma unroll
                for (int i = 0; i < 2; i++) {
                    int idx = tid + (i << 8);
                    int kr = idx >> 4, c4 = (idx & 15) << 2;
                    pb[i] = *(const float4*)(B + (long)(k0 + kr) * ldb + col0 + c4);
                }
            } else {
#pragma unroll
                for (int i = 0; i < 2; i++) {
                    int idx = tid + (i << 8);
                    int r = idx >> 3, c4 = (idx & 7) << 2;
                    pb[i] = *(const float4*)(B + (long)(col0 + r) * ldb + k0 + c4);
                }
            }
        }
        __syncthreads();

        // ---- MMA on smem chunk ----
#pragma unroll
        for (int kb = 0; kb < 2; kb++) {
            uint32_t aH[2][4], aL[2][4], bH[4][2], bL[4][2];
#pragma unroll
            for (int mi = 0; mi < 2; mi++) {
                uint32_t off = aOff + (uint32_t)(mi * 16 * LDS * 2 + kb * 32);
                ldm_x4(aH[mi], baseAh + off);
                ldm_x4(aL[mi], baseAl + off);
            }
#pragma unroll
            for (int nj = 0; nj < 4; nj++) {
                uint32_t off = bOffBase + (uint32_t)(nj * 8 * LDS * 2 + kb * 32);
                ldm_x2(bH[nj], baseBh + off);
                ldm_x2(bL[nj], baseBl + off);
            }
#pragma unroll
            for (int mi = 0; mi < 2; mi++)
#pragma unroll
                for (int nj = 0; nj < 4; nj++) {
                    mma_bf16(acc[mi][nj], aH[mi], bH[nj]);
                    mma_bf16(acc[mi][nj], aH[mi], bL[nj]);
                    mma_bf16(acc[mi][nj], aL[mi], bH[nj]);
                }
        }
        __syncthreads();
    }

    // ---- epilogue ----
    int rb = row0 + wm * 32 + (lane >> 2);
    int cb = col0 + wn * 32 + ((lane & 3) << 1);
#pragma unroll
    for (int mi = 0; mi < 2; mi++) {
#pragma unroll
        for (int half = 0; half < 2; half++) {
            int r = rb + mi * 16 + half * 8;
            int qAbs = maskRowOff + r;
            float* dst;
            int rr, ld;
            if (r < splitRow) { dst = Cd0; rr = r;            ld = ldc;  }
            else              { dst = D2;  rr = r - splitRow; ld = ldd2; }
#pragma unroll
            for (int nj = 0; nj < 4; nj++) {
                int c = cb + nj * 8;
                float2 v;
                v.x = acc[mi][nj][half * 2 + 0] * scale;
                v.y = acc[mi][nj][half * 2 + 1] * scale;
                if (causal) {
                    if (c + 0 > qAbs) v.x = -1e30f;
                    if (c + 1 > qAbs) v.y = -1e30f;
                }
                *(float2*)(dst + (long)rr * ld + c) = v;
                if (dupC) {
                    *(float2*)(Cd1 + (long)rr * ld + c) = v;
                    *(float2*)(Cd2 + (long)rr * ld + c) = v;
                }
            }
        }
    }
}

// ---------------- row softmax over 768 columns ------------------------------
__global__ void __launch_bounds__(256) softmax_rows(
    float* __restrict__ Sm, long zstride, int rowStart)
{
    float* row = Sm + (long)blockIdx.y * zstride + (long)(rowStart + blockIdx.x) * CL;
    int tid = threadIdx.x;
    __shared__ float red[256];

    float m = -1e30f;
    for (int c = tid; c < CL; c += 256) m = fmaxf(m, row[c]);
    red[tid] = m; __syncthreads();
    for (int s = 128; s > 0; s >>= 1) { if (tid < s) red[tid] = fmaxf(red[tid], red[tid + s]); __syncthreads(); }
    m = red[0]; __syncthreads();

    float sum = 0.f;
    for (int c = tid; c < CL; c += 256) { float e = __expf(row[c] - m); row[c] = e; sum += e; }
    red[tid] = sum; __syncthreads();
    for (int s = 128; s > 0; s >>= 1) { if (tid < s) red[tid] += red[tid + s]; __syncthreads(); }
    float inv = 1.f / red[0];
    for (int c = tid; c < CL; c += 256) row[c] *= inv;
}

// ---------------- small copy kernels ----------------------------------------
__global__ void bcast_state(const float* __restrict__ src, float* __restrict__ dst)
{
    int i = blockIdx.x * blockDim.x + threadIdx.x;
    if (i >= CSL * CD) return;
    dst[i] = src[i];
    dst[CSL * CD + i] = src[i];
}

__global__ void dup_tail(float* __restrict__ kk, float* __restrict__ qq, float* __restrict__ vv)
{
    int i = blockIdx.x * blockDim.x + threadIdx.x;
    if (i >= CBH * CSL * CDK) return;
    int c = i % CDK, r = (i / CDK) % CSL, z = i / (CDK * CSL);
    long src = ((long)z * CL + r) * CDK + c;
    long dst = ((long)z * CL + (CSL + CSEG) + r) * CDK + c;
    kk[dst] = kk[src]; qq[dst] = qq[src]; vv[dst] = vv[src];
}

__global__ void build_mid(const float* __restrict__ kf, const float* __restrict__ qf,
                          const float* __restrict__ vf,
                          float* __restrict__ kk, float* __restrict__ qq,
                          float* __restrict__ vv, int seg)
{
    int i = blockIdx.x * blockDim.x + threadIdx.x;
    if (i >= CBH * CSEG * CDK) return;
    int c = i % CDK, r = (i / CDK) % CSEG, z = i / (CDK * CSEG);
    long src = ((long)z * CS + seg * CSEG + r) * CDK + c;
    long dst = ((long)z * CL + CSL + r) * CDK + c;
    kk[dst] = kf[src]; qq[dst] = qf[src]; vv[dst] = vf[src];
}

// ---------------- host helpers ----------------------------------------------
struct GArg {
    const float *A; int lda; long sAb, sAh;
    const float *B0, *B1, *B2; int ldb; long sBb, sBh; int transB;
    float *C0, *C1, *C2; int ldc; long sC;
    float *D2; int ldd2; long sD2; int split;
    float scale; int causal, maskOff, trimK, dupC, Z, nh, groups;
};

static void gemm(int M, int N, int K, const GArg& a)
{
    dim3 g(M / 128, N / 64, a.groups * a.Z);
    mma_gemm<<<g, 256>>>(K, a.A, a.lda, a.sAb, a.sAh,
                         a.B0, a.B1, a.B2, a.ldb, a.sBb, a.sBh, a.transB,
                         a.C0, a.C1, a.C2, a.ldc, a.sC,
                         a.D2, a.ldd2, a.sD2, a.split,
                         a.scale, a.causal, a.maskOff, a.trimK, a.dupC,
                         a.nh, a.Z);
}

static float* sym_addr(const void* s)
{
    void* t = nullptr;
    cudaGetSymbolAddress(&t, s);
    return (float*)t;
}

extern "C" void kernel_launch(void* const* d_in, const int* in_sizes, int n_in,
                              void* d_out, int out_size)
{
    const float* x     = (const float*)d_in[0];
    const float* st0   = (const float*)d_in[1];
    const float* Wk    = (const float*)d_in[2];
    const float* Wq    = (const float*)d_in[3];
    const float* Wv    = (const float*)d_in[4];
    const float* W2k   = (const float*)d_in[5];
    const float* Wout  = (const float*)d_in[6];
    const float* Wks   = (const float*)d_in[7];
    const float* Wqs   = (const float*)d_in[8];
    const float* Wvs   = (const float*)d_in[9];
    const float* W2kss = (const float*)d_in[10];
    const float* W2qss = (const float*)d_in[11];
    const float* W2vss = (const float*)d_in[12];
    const float* W2kse = (const float*)d_in[13];
    const float* W2qse = (const float*)d_in[14];
    const float* W2vse = (const float*)d_in[15];
    const float* Wos   = (const float*)d_in[16];
    float* out = (float*)d_out;

    static float *kf = nullptr, *qf, *vf, *stb, *kk, *qq, *vv, *s1, *att1, *k2, *q2, *v2, *a2c, *a2e;
    if (!kf) {
        kf = sym_addr(g_kf);   qf = sym_addr(g_qf);   vf = sym_addr(g_vf);
        stb = sym_addr(g_state); kk = sym_addr(g_kk); qq = sym_addr(g_qq);
        vv = sym_addr(g_vv);   s1 = sym_addr(g_s1);   att1 = sym_addr(g_att1);
        k2 = sym_addr(g_k2);   q2 = sym_addr(g_q2);   v2 = sym_addr(g_v2);
        a2c = sym_addr(g_a2c); a2e = sym_addr(g_a2e);
    }

    const int BIG = 1 << 30;
    const float SC = 0.125f;
    const long WH = (long)CD * CDK;      // per-head 1024x64 weight
    const long W2H = (long)CDV * C2DV;   // per-head 64x128 weight

    // ---- full-sequence projections (one grouped launch) ----
    {
        GArg a{};
        a.A = x; a.lda = CD; a.sAb = (long)CS * CD; a.sAh = 0;
        a.B0 = Wk; a.B1 = Wq; a.B2 = Wv; a.ldb = CDK; a.sBb = 0; a.sBh = WH; a.transB = 1;
        a.C0 = kf; a.C1 = qf; a.C2 = vf; a.ldc = CDK; a.sC = (long)CS * CDK;
        a.split = BIG; a.scale = 1.f; a.Z = CBH; a.nh = CH; a.groups = 3;
        gemm(CS, CDK, CD, a);
    }

    bcast_state<<<(CSL * CD + 255) / 256, 256>>>(st0, stb);

    for (int seg = 0; seg < 4; seg++) {
        // ---- state projections (one grouped launch) ----
        {
            GArg a{};
            a.A = stb; a.lda = CD; a.sAb = (long)CSL * CD; a.sAh = 0;
            a.B0 = Wks; a.B1 = Wqs; a.B2 = Wvs; a.ldb = CDK; a.sBb = 0; a.sBh = WH; a.transB = 1;
            a.C0 = kk; a.C1 = qq; a.C2 = vv; a.ldc = CDK; a.sC = (long)CL * CDK;
            a.split = BIG; a.scale = 1.f; a.Z = CBH; a.nh = CH; a.groups = 3;
            gemm(CSL, CDK, CD, a);
        }
        dup_tail<<<(CBH * CSL * CDK + 255) / 256, 256>>>(kk, qq, vv);
        build_mid<<<(CBH * CSEG * CDK + 255) / 256, 256>>>(kf, qf, vf, kk, qq, vv, seg);

        // ---- attention 1: QK^T (causal, skip masked tiles) ----
        {
            GArg a{};
            a.A = qq; a.lda = CDK; a.sAb = (long)CL * CDK; a.sAh = 0;
            a.B0 = kk; a.ldb = CDK; a.sBb = (long)CL * CDK; a.sBh = 0; a.transB = 0;
            a.C0 = s1; a.ldc = CL; a.sC = (long)CL * CL;
            a.split = BIG; a.scale = SC; a.causal = 1; a.maskOff = 0;
            a.Z = CBH; a.nh = 1; a.groups = 1;
            gemm(CL, CL, CDK, a);
        }
        softmax_rows<<<dim3(CL, CBH), 256>>>(s1, (long)CL * CL, 0);
        // ---- P @ V (K trimmed to causal extent) ----
        {
            GArg a{};
            a.A = s1; a.lda = CL; a.sAb = (long)CL * CL; a.sAh = 0;
            a.B0 = vv; a.ldb = CDV; a.sBb = (long)CL * CDV; a.sBh = 0; a.transB = 1;
            a.C0 = att1; a.ldc = CDV; a.sC = (long)CL * CDV;
            a.split = BIG; a.scale = 1.f; a.trimK = 1; a.maskOff = 0;
            a.Z = CBH; a.nh = 1; a.groups = 1;
            gemm(CL, CDV, CL, a);
        }

        // ---- second projections ----
        const long sA1b = (long)CH * CL * CDV, sA1h = (long)CL * CDV;
        {   // start-slice: 3 weights, one launch
            GArg a{};
            a.A = att1; a.lda = CDV; a.sAb = sA1b; a.sAh = sA1h;
            a.B0 = W2kss; a.B1 = W2qss; a.B2 = W2vss; a.ldb = C2DV; a.sBb = 0; a.sBh = W2H; a.transB = 1;
            a.C0 = k2; a.C1 = q2; a.C2 = v2; a.ldc = C2DV; a.sC = (long)CL * C2DV;
            a.split = BIG; a.scale = 1.f; a.Z = CBH; a.nh = CH; a.groups = 3;
            gemm(CSL, C2DV, CDV, a);
        }
        {   // mid: W2k for k2/q2/v2 (reference quirk) — compute once, triple-store
            GArg a{};
            a.A = att1 + (long)CSL * CDV; a.lda = CDV; a.sAb = sA1b; a.sAh = sA1h;
            a.B0 = W2k; a.ldb = C2DV; a.sBb = 0; a.sBh = W2H; a.transB = 1;
            a.C0 = k2 + (long)CSL * C2DV; a.C1 = q2 + (long)CSL * C2DV; a.C2 = v2 + (long)CSL * C2DV;
            a.ldc = C2DV; a.sC = (long)CL * C2DV;
            a.split = BIG; a.scale = 1.f; a.dupC = 1; a.Z = CBH; a.nh = CH; a.groups = 1;
            gemm(CSEG, C2DV, CDV, a);
        }
        {   // end-slice: 3 weights, one launch
            GArg a{};
            a.A = att1 + (long)(CSL + CSEG) * CDV; a.lda = CDV; a.sAb = sA1b; a.sAh = sA1h;
            a.B0 = W2kse; a.B1 = W2qse; a.B2 = W2vse; a.ldb = C2DV; a.sBb = 0; a.sBh = W2H; a.transB = 1;
            a.C0 = k2 + (long)(CSL + CSEG) * C2DV; a.C1 = q2 + (long)(CSL + CSEG) * C2DV;
            a.C2 = v2 + (long)(CSL + CSEG) * C2DV; a.ldc = C2DV; a.sC = (long)CL * C2DV;
            a.split = BIG; a.scale = 1.f; a.Z = CBH; a.nh = CH; a.groups = 3;
            gemm(CSL, C2DV, CDV, a);
        }

        // ---- attention 2: queries 128..767 ----
        {
            GArg a{};
            a.A = q2 + (long)CSL * C2DV; a.lda = C2DV; a.sAb = (long)CL * C2DV; a.sAh = 0;
            a.B0 = k2; a.ldb = C2DV; a.sBb = (long)CL * C2DV; a.sBh = 0; a.transB = 0;
            a.C0 = s1 + (long)CSL * CL; a.ldc = CL; a.sC = (long)CL * CL;
            a.split = BIG; a.scale = SC; a.causal = 1; a.maskOff = CSL;
            a.Z = CBH; a.nh = 1; a.groups = 1;
            gemm(CL - CSL, CL, C2DV, a);
        }
        softmax_rows<<<dim3(CL - CSL, CBH), 256>>>(s1, (long)CL * CL, CSL);
        {   // P2 @ V2 (trimmed K), split store mid->a2c, end->a2e
            GArg a{};
            a.A = s1 + (long)CSL * CL; a.lda = CL; a.sAb = (long)CL * CL; a.sAh = 0;
            a.B0 = v2; a.ldb = C2DV; a.sBb = (long)CL * C2DV; a.sBh = 0; a.transB = 1;
            a.C0 = a2c; a.ldc = C2DV; a.sC = (long)CSEG * C2DV;
            a.D2 = a2e; a.ldd2 = C2DV; a.sD2 = (long)CSL * C2DV; a.split = CSEG;
            a.scale = 1.f; a.trimK = 1; a.maskOff = CSL;
            a.Z = CBH; a.nh = 1; a.groups = 1;
            gemm(CL - CSL, C2DV, CL, a);
        }

        // ---- output GEMM: per-b [512 x 2048] @ Wout[2048 x 1024] ----
        {
            GArg a{};
            a.A = a2c; a.lda = 2 * CH * CDV; a.sAb = (long)CH * CSEG * C2DV; a.sAh = 0;
            a.B0 = Wout; a.ldb = CD; a.sBb = 0; a.sBh = 0; a.transB = 1;
            a.C0 = out + (long)seg * CSEG * CD; a.ldc = CD; a.sC = (long)CS * CD;
            a.split = BIG; a.scale = 1.f; a.Z = CB; a.nh = 1; a.groups = 1;
            gemm(CSEG, CD, 2 * CH * CDV, a);
        }
        // ---- state GEMM ----
        {
            float* dst = (seg < 3) ? stb : (out + (long)CB * CS * CD);
            GArg a{};
            a.A = a2e; a.lda = 2 * CH * CDV; a.sAb = (long)CH * CSL * C2DV; a.sAh = 0;
            a.B0 = Wos; a.ldb = CD; a.sBb = 0; a.sBh = 0; a.transB = 1;
            a.C0 = dst; a.ldc = CD; a.sC = (long)CSL * CD;
            a.split = BIG; a.scale = 1.f; a.Z = CB; a.nh = 1; a.groups = 1;
            gemm(CSL, CD, 2 * CH * CDV, a);
        }
    }
}

// round 9
// speedup vs baseline: 2.3819x; 1.2568x over previous
#include <cuda_runtime.h>
#include <cuda_bf16.h>
#include <cstdint>

// ---------------- problem constants ----------------
#define CB   2
#define CS   2048
#define CD   1024
#define CH   16
#define CDK  64
#define CDV  64
#define CSEG 512
#define CSL  128
#define CL   768          // SL + SEG + SL
#define CBH  32           // B*H
#define C2DV 128          // 2*DV

// ---------------- scratch (device globals) ----------------------------------
__device__ float g_kf[CB*CH*CS*CDK];
__device__ float g_qf[CB*CH*CS*CDK];
__device__ float g_vf[CB*CH*CS*CDV];
__device__ float g_state[CB*CSL*CD];
__device__ float g_kk[CBH*CL*CDK];
__device__ float g_qq[CBH*CL*CDK];
__device__ float g_vv[CBH*CL*CDV];
__device__ float g_att1[CBH*CL*CDV];
__device__ float g_k2[CBH*CL*C2DV];
__device__ float g_q2[CBH*CL*C2DV];
__device__ float g_v2[CBH*CL*C2DV];
__device__ float g_a2c[CB*CH*CSEG*C2DV];
__device__ float g_a2e[CB*CH*CSL*C2DV];

// ---------------- helpers ----------------------------------------------------
__device__ __forceinline__ uint32_t smem_u32(const void* p) {
    uint32_t a;
    asm("{ .reg .u64 t; cvta.to.shared.u64 t, %1; cvt.u32.u64 %0, t; }" : "=r"(a) : "l"(p));
    return a;
}
__device__ __forceinline__ void ldm_x4(uint32_t* r, uint32_t addr) {
    asm volatile("ldmatrix.sync.aligned.m8n8.x4.shared.b16 {%0,%1,%2,%3}, [%4];"
                 : "=r"(r[0]), "=r"(r[1]), "=r"(r[2]), "=r"(r[3]) : "r"(addr));
}
__device__ __forceinline__ void ldm_x2(uint32_t* r, uint32_t addr) {
    asm volatile("ldmatrix.sync.aligned.m8n8.x2.shared.b16 {%0,%1}, [%2];"
                 : "=r"(r[0]), "=r"(r[1]) : "r"(addr));
}
__device__ __forceinline__ void ldm_x2_t(uint32_t* r, uint32_t addr) {
    asm volatile("ldmatrix.sync.aligned.m8n8.x2.trans.shared.b16 {%0,%1}, [%2];"
                 : "=r"(r[0]), "=r"(r[1]) : "r"(addr));
}
__device__ __forceinline__ void mma_bf16(float* d, const uint32_t* a, const uint32_t* b) {
    asm volatile("mma.sync.aligned.m16n8k16.row.col.f32.bf16.bf16.f32 "
                 "{%0,%1,%2,%3}, {%4,%5,%6,%7}, {%8,%9}, {%0,%1,%2,%3};"
                 : "+f"(d[0]), "+f"(d[1]), "+f"(d[2]), "+f"(d[3])
                 : "r"(a[0]), "r"(a[1]), "r"(a[2]), "r"(a[3]), "r"(b[0]), "r"(b[1]));
}
__device__ __forceinline__ void split2(float x, float y, uint32_t& hi, uint32_t& lo) {
    __nv_bfloat16 hx = __float2bfloat16_rn(x), hy = __float2bfloat16_rn(y);
    __nv_bfloat16 lx = __float2bfloat16_rn(x - __bfloat162float(hx));
    __nv_bfloat16 ly = __float2bfloat16_rn(y - __bfloat162float(hy));
    hi = ((uint32_t)__bfloat16_as_ushort(hy) << 16) | __bfloat16_as_ushort(hx);
    lo = ((uint32_t)__bfloat16_as_ushort(ly) << 16) | __bfloat16_as_ushort(lx);
}

// ---------------- fused flash attention --------------------------------------
// O = softmax(causal(Q K^T / 8)) V, all fp32 in gmem; bf16 hi/lo MMAs inside.
// CTA: 128 query rows, 8 warps x 16 rows. Key blocks of 64. grid=(M/128, Z).
// Q: [z][M][E] (ld=E), K/V: [z][CL][E]. maskOff: abs query = maskOff + row.
// Split store: local row >= splitRow -> O2 at (row - splitRow).
template<int E>
__global__ void __launch_bounds__(256) flash_attn(
    const float* __restrict__ Q, long sQ,
    const float* __restrict__ K, long sK,
    const float* __restrict__ V, long sV,
    float* __restrict__ O0, int ldo, long sO,
    float* __restrict__ O2, int ldo2, long sO2, int splitRow,
    int maskOff)
{
    constexpr int SK = E + 8;          // bf16 row stride
    constexpr int NB = E / 8;          // out-col blocks
    extern __shared__ __nv_bfloat16 sm[];
    __nv_bfloat16 *qh = sm,            *ql = sm + 128 * SK;
    __nv_bfloat16 *kh = sm + 256 * SK, *kl = kh + 64 * SK;
    __nv_bfloat16 *vh = kl + 64 * SK,  *vl = vh + 64 * SK;

    int z = blockIdx.y;
    Q += z * sQ; K += z * sK; V += z * sV;
    O0 += z * sO;
    if (O2) O2 += z * sO2;

    int tid = threadIdx.x, lane = tid & 31, wid = tid >> 5;
    int row0 = blockIdx.x * 128;

    // ---- load Q tile (128 x E) -> hi/lo smem ----
#pragma unroll
    for (int i = 0; i < E / 8; i++) {
        int idx = tid + (i << 8);
        int r = idx / (E / 4), c4 = (idx % (E / 4)) << 2;
        float4 v = *(const float4*)(Q + (long)(row0 + r) * E + c4);
        uint32_t h01, l01, h23, l23;
        split2(v.x, v.y, h01, l01);
        split2(v.z, v.w, h23, l23);
        *(uint2*)&qh[r * SK + c4] = make_uint2(h01, h23);
        *(uint2*)&ql[r * SK + c4] = make_uint2(l01, l23);
    }

    uint32_t bQh = smem_u32(qh), bQl = smem_u32(ql);
    uint32_t bKh = smem_u32(kh), bKl = smem_u32(kl);
    uint32_t bVh = smem_u32(vh), bVl = smem_u32(vl);

    // ldmatrix lane offsets (bytes)
    uint32_t aOff = (uint32_t)((wid * 16 + (lane & 15)) * SK * 2 + (lane >> 4) * 16);
    uint32_t bOff = (uint32_t)((lane & 7) * SK * 2 + ((lane >> 3) & 1) * 16);
    uint32_t vOff = (uint32_t)((lane & 15) * SK * 2);

    float o[NB][4];
#pragma unroll
    for (int nb = 0; nb < NB; nb++)
#pragma unroll
        for (int q = 0; q < 4; q++) o[nb][q] = 0.f;
    float m0 = -1e30f, m1 = -1e30f, l0 = 0.f, l1 = 0.f;

    int g = lane >> 2, t2 = (lane & 3) << 1;
    int qA0 = maskOff + row0 + wid * 16 + g;
    int qA1 = qA0 + 8;
    int qMax = maskOff + row0 + 127;
    int nblk = ((qMax + 1 < CL ? qMax + 1 : CL) + 63) >> 6;

    for (int blk = 0; blk < nblk; blk++) {
        __syncthreads();
        // ---- load K,V block (64 x E) -> hi/lo smem ----
#pragma unroll
        for (int i = 0; i < E / 16; i++) {
            int idx = tid + (i << 8);
            int r = idx / (E / 4), c4 = (idx % (E / 4)) << 2;
            long gofs = (long)(blk * 64 + r) * E + c4;
            float4 kv = *(const float4*)(K + gofs);
            uint32_t h01, l01, h23, l23;
            split2(kv.x, kv.y, h01, l01);
            split2(kv.z, kv.w, h23, l23);
            *(uint2*)&kh[r * SK + c4] = make_uint2(h01, h23);
            *(uint2*)&kl[r * SK + c4] = make_uint2(l01, l23);
            float4 vv4 = *(const float4*)(V + gofs);
            split2(vv4.x, vv4.y, h01, l01);
            split2(vv4.z, vv4.w, h23, l23);
            *(uint2*)&vh[r * SK + c4] = make_uint2(h01, h23);
            *(uint2*)&vl[r * SK + c4] = make_uint2(l01, l23);
        }
        __syncthreads();

        // ---- S = Q K^T (16 x 64 per warp) ----
        float s[8][4];
#pragma unroll
        for (int nj = 0; nj < 8; nj++)
#pragma unroll
            for (int q = 0; q < 4; q++) s[nj][q] = 0.f;
#pragma unroll
        for (int ks = 0; ks < E / 16; ks++) {
            uint32_t aH[4], aL[4];
            ldm_x4(aH, bQh + aOff + ks * 32);
            ldm_x4(aL, bQl + aOff + ks * 32);
#pragma unroll
            for (int nj = 0; nj < 8; nj++) {
                uint32_t bH[2], bL[2];
                uint32_t off = bOff + (uint32_t)(nj * 8 * SK * 2 + ks * 32);
                ldm_x2(bH, bKh + off);
                ldm_x2(bL, bKl + off);
                mma_bf16(s[nj], aH, bH);
                mma_bf16(s[nj], aH, bL);
                mma_bf16(s[nj], aL, bH);
            }
        }

        // ---- scale + causal mask + row max ----
        float mx0 = -1e30f, mx1 = -1e30f;
#pragma unroll
        for (int nj = 0; nj < 8; nj++) {
            int cb = blk * 64 + nj * 8 + t2;
#pragma unroll
            for (int q = 0; q < 4; q++) {
                int c = cb + (q & 1);
                float val = s[nj][q] * 0.125f;
                if (c > ((q < 2) ? qA0 : qA1)) val = -1e30f;
                s[nj][q] = val;
                if (q < 2) { if (val > mx0) mx0 = val; }
                else       { if (val > mx1) mx1 = val; }
            }
        }
        mx0 = fmaxf(mx0, __shfl_xor_sync(0xFFFFFFFF, mx0, 1));
        mx0 = fmaxf(mx0, __shfl_xor_sync(0xFFFFFFFF, mx0, 2));
        mx1 = fmaxf(mx1, __shfl_xor_sync(0xFFFFFFFF, mx1, 1));
        mx1 = fmaxf(mx1, __shfl_xor_sync(0xFFFFFFFF, mx1, 2));

        float mn0 = fmaxf(m0, mx0), mn1 = fmaxf(m1, mx1);
        float al0 = __expf(m0 - mn0), al1 = __expf(m1 - mn1);
        m0 = mn0; m1 = mn1;

        // ---- P = exp(S - m), row sum ----
        float rs0 = 0.f, rs1 = 0.f;
#pragma unroll
        for (int nj = 0; nj < 8; nj++) {
#pragma unroll
            for (int q = 0; q < 4; q++) {
                float p = __expf(s[nj][q] - ((q < 2) ? m0 : m1));
                s[nj][q] = p;
                if (q < 2) rs0 += p; else rs1 += p;
            }
        }
        rs0 += __shfl_xor_sync(0xFFFFFFFF, rs0, 1);
        rs0 += __shfl_xor_sync(0xFFFFFFFF, rs0, 2);
        rs1 += __shfl_xor_sync(0xFFFFFFFF, rs1, 1);
        rs1 += __shfl_xor_sync(0xFFFFFFFF, rs1, 2);
        l0 = l0 * al0 + rs0;
        l1 = l1 * al1 + rs1;

        // ---- rescale O ----
#pragma unroll
        for (int nb = 0; nb < NB; nb++) {
            o[nb][0] *= al0; o[nb][1] *= al0;
            o[nb][2] *= al1; o[nb][3] *= al1;
        }

        // ---- O += P V ----
#pragma unroll
        for (int j = 0; j < 4; j++) {
            uint32_t aH[4], aL[4];
            split2(s[2 * j][0],     s[2 * j][1],     aH[0], aL[0]);
            split2(s[2 * j][2],     s[2 * j][3],     aH[1], aL[1]);
            split2(s[2 * j + 1][0], s[2 * j + 1][1], aH[2], aL[2]);
            split2(s[2 * j + 1][2], s[2 * j + 1][3], aH[3], aL[3]);
#pragma unroll
            for (int nb = 0; nb < NB; nb++) {
                uint32_t bH[2], bL[2];
                uint32_t off = vOff + (uint32_t)(j * 16 * SK * 2 + nb * 16);
                ldm_x2_t(bH, bVh + off);
                ldm_x2_t(bL, bVl + off);
                mma_bf16(o[nb], aH, bH);
                mma_bf16(o[nb], aH, bL);
                mma_bf16(o[nb], aL, bH);
            }
        }
    }

    // ---- epilogue: O /= l, split store ----
    float inv0 = 1.f / l0, inv1 = 1.f / l1;
    int r0 = row0 + wid * 16 + g;
    int r1 = r0 + 8;
    float *d0, *d1;
    int rr0, rr1, ldx0, ldx1;
    if (r0 < splitRow) { d0 = O0; rr0 = r0; ldx0 = ldo; }
    else               { d0 = O2; rr0 = r0 - splitRow; ldx0 = ldo2; }
    if (r1 < splitRow) { d1 = O0; rr1 = r1; ldx1 = ldo; }
    else               { d1 = O2; rr1 = r1 - splitRow; ldx1 = ldo2; }
#pragma unroll
    for (int nb = 0; nb < NB; nb++) {
        int c = nb * 8 + t2;
        *(float2*)(d0 + (long)rr0 * ldx0 + c) = make_float2(o[nb][0] * inv0, o[nb][1] * inv0);
        *(float2*)(d1 + (long)rr1 * ldx1 + c) = make_float2(o[nb][2] * inv1, o[nb][3] * inv1);
    }
}

// ---------------- unified tensor-core GEMM (unchanged from R8) ---------------
#define LDS 40

__global__ void __launch_bounds__(256) mma_gemm(
    int K,
    const float* __restrict__ A, int lda, long sAb, long sAh,
    const float* __restrict__ B0, const float* __restrict__ B1, const float* __restrict__ B2,
    int ldb, long sBb, long sBh, int transB,
    float* __restrict__ C0, float* __restrict__ C1, float* __restrict__ C2c,
    int ldc, long sC, int dupC, int nh, int zPer)
{
    __shared__ __nv_bfloat16 sAh_[128 * LDS], sAl_[128 * LDS];
    __shared__ __nv_bfloat16 sBh_[64 * LDS],  sBl_[64 * LDS];

    int zz = blockIdx.z;
    int g = zz / zPer, z = zz - g * zPer;
    int b = z / nh, h = z - b * nh;

    const float* B = (g == 0) ? B0 : ((g == 1) ? B1 : B2);
    A += (long)b * sAb + (long)h * sAh;
    B += (long)b * sBb + (long)h * sBh;

    float *Cd0, *Cd1 = nullptr, *Cd2 = nullptr;
    if (dupC) {
        Cd0 = C0 + (long)z * sC; Cd1 = C1 + (long)z * sC; Cd2 = C2c + (long)z * sC;
    } else {
        float* Cs = (g == 0) ? C0 : ((g == 1) ? C1 : C2c);
        Cd0 = Cs + (long)z * sC;
    }

    int tid = threadIdx.x;
    int lane = tid & 31, w = tid >> 5;
    int wm = w & 3, wn = w >> 2;
    int row0 = blockIdx.x * 128, col0 = blockIdx.y * 64;

    int nchunk = K >> 5;

    uint32_t baseAh = smem_u32(sAh_), baseAl = smem_u32(sAl_);
    uint32_t baseBh = smem_u32(sBh_), baseBl = smem_u32(sBl_);
    uint32_t aOff = (uint32_t)((wm * 32 + (lane & 15)) * LDS * 2 + (lane >> 4) * 16);
    uint32_t bOffBase = (uint32_t)((wn * 32 + (lane & 7)) * LDS * 2 + ((lane >> 3) & 1) * 16);

    float acc[2][4][4];
#pragma unroll
    for (int mi = 0; mi < 2; mi++)
#pragma unroll
        for (int nj = 0; nj < 4; nj++)
#pragma unroll
            for (int q = 0; q < 4; q++) acc[mi][nj][q] = 0.f;

    float4 pa[4], pb[2];
    {
#pragma unroll
        for (int i = 0; i < 4; i++) {
            int idx = tid + (i << 8);
            int r = idx >> 3, c4 = (idx & 7) << 2;
            pa[i] = *(const float4*)(A + (long)(row0 + r) * lda + c4);
        }
        if (transB) {
#pragma unroll
            for (int i = 0; i < 2; i++) {
                int idx = tid + (i << 8);
                int kr = idx >> 4, c4 = (idx & 15) << 2;
                pb[i] = *(const float4*)(B + (long)kr * ldb + col0 + c4);
            }
        } else {
#pragma unroll
            for (int i = 0; i < 2; i++) {
                int idx = tid + (i << 8);
                int r = idx >> 3, c4 = (idx & 7) << 2;
                pb[i] = *(const float4*)(B + (long)(col0 + r) * ldb + c4);
            }
        }
    }

    for (int ch = 0; ch < nchunk; ch++) {
#pragma unroll
        for (int i = 0; i < 4; i++) {
            int idx = tid + (i << 8);
            int r = idx >> 3, c4 = (idx & 7) << 2;
            uint32_t h01, l01, h23, l23;
            split2(pa[i].x, pa[i].y, h01, l01);
            split2(pa[i].z, pa[i].w, h23, l23);
            *(uint2*)&sAh_[r * LDS + c4] = make_uint2(h01, h23);
            *(uint2*)&sAl_[r * LDS + c4] = make_uint2(l01, l23);
        }
        if (transB) {
#pragma unroll
            for (int i = 0; i < 2; i++) {
                int idx = tid + (i << 8);
                int kr = idx >> 4, c4 = (idx & 15) << 2;
                float vv4[4] = { pb[i].x, pb[i].y, pb[i].z, pb[i].w };
#pragma unroll
                for (int j = 0; j < 4; j++) {
                    __nv_bfloat16 hh = __float2bfloat16_rn(vv4[j]);
                    __nv_bfloat16 ll = __float2bfloat16_rn(vv4[j] - __bfloat162float(hh));
                    sBh_[(c4 + j) * LDS + kr] = hh;
                    sBl_[(c4 + j) * LDS + kr] = ll;
                }
            }
        } else {
#pragma unroll
            for (int i = 0; i < 2; i++) {
                int idx = tid + (i << 8);
                int r = idx >> 3, c4 = (idx & 7) << 2;
                uint32_t h01, l01, h23, l23;
                split2(pb[i].x, pb[i].y, h01, l01);
                split2(pb[i].z, pb[i].w, h23, l23);
                *(uint2*)&sBh_[r * LDS + c4] = make_uint2(h01, h23);
                *(uint2*)&sBl_[r * LDS + c4] = make_uint2(l01, l23);
            }
        }
        if (ch + 1 < nchunk) {
            int k0 = (ch + 1) << 5;
#pragma unroll
            for (int i = 0; i < 4; i++) {
                int idx = tid + (i << 8);
                int r = idx >> 3, c4 = (idx & 7) << 2;
                pa[i] = *(const float4*)(A + (long)(row0 + r) * lda + k0 + c4);
            }
            if (transB) {
#pragma unroll
                for (int i = 0; i < 2; i++) {
                    int idx = tid + (i << 8);
                    int kr = idx >> 4, c4 = (idx & 15) << 2;
                    pb[i] = *(const float4*)(B + (long)(k0 + kr) * ldb + col0 + c4);
                }
            } else {
#pragma unroll
                for (int i = 0; i < 2; i++) {
                    int idx = tid + (i << 8);
                    int r = idx >> 3, c4 = (idx & 7) << 2;
                    pb[i] = *(const float4*)(B + (long)(col0 + r) * ldb + k0 + c4);
                }
            }
        }
        __syncthreads();

#pragma unroll
        for (int kb = 0; kb < 2; kb++) {
            uint32_t aH[2][4], aL[2][4], bH[4][2], bL[4][2];
#pragma unroll
            for (int mi = 0; mi < 2; mi++) {
                uint32_t off = aOff + (uint32_t)(mi * 16 * LDS * 2 + kb * 32);
                ldm_x4(aH[mi], baseAh + off);
                ldm_x4(aL[mi], baseAl + off);
            }
#pragma unroll
            for (int nj = 0; nj < 4; nj++) {
                uint32_t off = bOffBase + (uint32_t)(nj * 8 * LDS * 2 + kb * 32);
                ldm_x2(bH[nj], baseBh + off);
                ldm_x2(bL[nj], baseBl + off);
            }
#pragma unroll
            for (int mi = 0; mi < 2; mi++)
#pragma unroll
                for (int nj = 0; nj < 4; nj++) {
                    mma_bf16(acc[mi][nj], aH[mi], bH[nj]);
                    mma_bf16(acc[mi][nj], aH[mi], bL[nj]);
                    mma_bf16(acc[mi][nj], aL[mi], bH[nj]);
                }
        }
        __syncthreads();
    }

    int rb = row0 + wm * 32 + (lane >> 2);
    int cb = col0 + wn * 32 + ((lane & 3) << 1);
#pragma unroll
    for (int mi = 0; mi < 2; mi++) {
#pragma unroll
        for (int half = 0; half < 2; half++) {
            int r = rb + mi * 16 + half * 8;
#pragma unroll
            for (int nj = 0; nj < 4; nj++) {
                int c = cb + nj * 8;
                float2 v;
                v.x = acc[mi][nj][half * 2 + 0];
                v.y = acc[mi][nj][half * 2 + 1];
                *(float2*)(Cd0 + (long)r * ldc + c) = v;
                if (dupC) {
                    *(float2*)(Cd1 + (long)r * ldc + c) = v;
                    *(float2*)(Cd2 + (long)r * ldc + c) = v;
                }
            }
        }
    }
}

// ---------------- small copy kernels ----------------------------------------
__global__ void bcast_state(const float* __restrict__ src, float* __restrict__ dst)
{
    int i = blockIdx.x * blockDim.x + threadIdx.x;
    if (i >= CSL * CD) return;
    dst[i] = src[i];
    dst[CSL * CD + i] = src[i];
}

__global__ void dup_tail(float* __restrict__ kk, float* __restrict__ qq, float* __restrict__ vv)
{
    int i = blockIdx.x * blockDim.x + threadIdx.x;
    if (i >= CBH * CSL * CDK) return;
    int c = i % CDK, r = (i / CDK) % CSL, z = i / (CDK * CSL);
    long src = ((long)z * CL + r) * CDK + c;
    long dst = ((long)z * CL + (CSL + CSEG) + r) * CDK + c;
    kk[dst] = kk[src]; qq[dst] = qq[src]; vv[dst] = vv[src];
}

__global__ void build_mid(const float* __restrict__ kf, const float* __restrict__ qf,
                          const float* __restrict__ vf,
                          float* __restrict__ kk, float* __restrict__ qq,
                          float* __restrict__ vv, int seg)
{
    int i = blockIdx.x * blockDim.x + threadIdx.x;
    if (i >= CBH * CSEG * CDK) return;
    int c = i % CDK, r = (i / CDK) % CSEG, z = i / (CDK * CSEG);
    long src = ((long)z * CS + seg * CSEG + r) * CDK + c;
    long dst = ((long)z * CL + CSL + r) * CDK + c;
    kk[dst] = kf[src]; qq[dst] = qf[src]; vv[dst] = vf[src];
}

// ---------------- host helpers ----------------------------------------------
struct GArg {
    const float *A; int lda; long sAb, sAh;
    const float *B0, *B1, *B2; int ldb; long sBb, sBh; int transB;
    float *C0, *C1, *C2; int ldc; long sC;
    int dupC, Z, nh, groups;
};

static void gemm(int M, int N, int K, const GArg& a)
{
    dim3 g(M / 128, N / 64, a.groups * a.Z);
    mma_gemm<<<g, 256>>>(K, a.A, a.lda, a.sAb, a.sAh,
                         a.B0, a.B1, a.B2, a.ldb, a.sBb, a.sBh, a.transB,
                         a.C0, a.C1, a.C2, a.ldc, a.sC,
                         a.dupC, a.nh, a.Z);
}

static float* sym_addr(const void* s)
{
    void* t = nullptr;
    cudaGetSymbolAddress(&t, s);
    return (float*)t;
}

extern "C" void kernel_launch(void* const* d_in, const int* in_sizes, int n_in,
                              void* d_out, int out_size)
{
    const float* x     = (const float*)d_in[0];
    const float* st0   = (const float*)d_in[1];
    const float* Wk    = (const float*)d_in[2];
    const float* Wq    = (const float*)d_in[3];
    const float* Wv    = (const float*)d_in[4];
    const float* W2k   = (const float*)d_in[5];
    const float* Wout  = (const float*)d_in[6];
    const float* Wks   = (const float*)d_in[7];
    const float* Wqs   = (const float*)d_in[8];
    const float* Wvs   = (const float*)d_in[9];
    const float* W2kss = (const float*)d_in[10];
    const float* W2qss = (const float*)d_in[11];
    const float* W2vss = (const float*)d_in[12];
    const float* W2kse = (const float*)d_in[13];
    const float* W2qse = (const float*)d_in[14];
    const float* W2vse = (const float*)d_in[15];
    const float* Wos   = (const float*)d_in[16];
    float* out = (float*)d_out;

    static float *kf = nullptr, *qf, *vf, *stb, *kk, *qq, *vv, *att1, *k2, *q2, *v2, *a2c, *a2e;
    if (!kf) {
        kf = sym_addr(g_kf);   qf = sym_addr(g_qf);   vf = sym_addr(g_vf);
        stb = sym_addr(g_state); kk = sym_addr(g_kk); qq = sym_addr(g_qq);
        vv = sym_addr(g_vv);   att1 = sym_addr(g_att1);
        k2 = sym_addr(g_k2);   q2 = sym_addr(g_q2);   v2 = sym_addr(g_v2);
        a2c = sym_addr(g_a2c); a2e = sym_addr(g_a2e);
        cudaFuncSetAttribute(flash_attn<64>,  cudaFuncAttributeMaxDynamicSharedMemorySize, 768 * (64 + 8) * 2);
        cudaFuncSetAttribute(flash_attn<128>, cudaFuncAttributeMaxDynamicSharedMemorySize, 768 * (128 + 8) * 2);
    }

    const int BIG = 1 << 30;
    const long WH = (long)CD * CDK;
    const long W2H = (long)CDV * C2DV;

    // ---- full-sequence projections (one grouped launch) ----
    {
        GArg a{};
        a.A = x; a.lda = CD; a.sAb = (long)CS * CD; a.sAh = 0;
        a.B0 = Wk; a.B1 = Wq; a.B2 = Wv; a.ldb = CDK; a.sBb = 0; a.sBh = WH; a.transB = 1;
        a.C0 = kf; a.C1 = qf; a.C2 = vf; a.ldc = CDK; a.sC = (long)CS * CDK;
        a.Z = CBH; a.nh = CH; a.groups = 3;
        gemm(CS, CDK, CD, a);
    }

    bcast_state<<<(CSL * CD + 255) / 256, 256>>>(st0, stb);

    for (int seg = 0; seg < 4; seg++) {
        // ---- state projections ----
        {
            GArg a{};
            a.A = stb; a.lda = CD; a.sAb = (long)CSL * CD; a.sAh = 0;
            a.B0 = Wks; a.B1 = Wqs; a.B2 = Wvs; a.ldb = CDK; a.sBb = 0; a.sBh = WH; a.transB = 1;
            a.C0 = kk; a.C1 = qq; a.C2 = vv; a.ldc = CDK; a.sC = (long)CL * CDK;
            a.Z = CBH; a.nh = CH; a.groups = 3;
            gemm(CSL, CDK, CD, a);
        }
        dup_tail<<<(CBH * CSL * CDK + 255) / 256, 256>>>(kk, qq, vv);
        build_mid<<<(CBH * CSEG * CDK + 255) / 256, 256>>>(kf, qf, vf, kk, qq, vv, seg);

        // ---- attention 1 (fused) ----
        {
            dim3 g(CL / 128, CBH);
            flash_attn<64><<<g, 256, 768 * (64 + 8) * 2>>>(
                qq, (long)CL * CDK, kk, (long)CL * CDK, vv, (long)CL * CDV,
                att1, CDV, (long)CL * CDV,
                nullptr, 0, 0, BIG, 0);
        }

        // ---- second projections ----
        const long sA1b = (long)CH * CL * CDV, sA1h = (long)CL * CDV;
        {
            GArg a{};
            a.A = att1; a.lda = CDV; a.sAb = sA1b; a.sAh = sA1h;
            a.B0 = W2kss; a.B1 = W2qss; a.B2 = W2vss; a.ldb = C2DV; a.sBb = 0; a.sBh = W2H; a.transB = 1;
            a.C0 = k2; a.C1 = q2; a.C2 = v2; a.ldc = C2DV; a.sC = (long)CL * C2DV;
            a.Z = CBH; a.nh = CH; a.groups = 3;
            gemm(CSL, C2DV, CDV, a);
        }
        {
            GArg a{};
            a.A = att1 + (long)CSL * CDV; a.lda = CDV; a.sAb = sA1b; a.sAh = sA1h;
            a.B0 = W2k; a.ldb = C2DV; a.sBb = 0; a.sBh = W2H; a.transB = 1;
            a.C0 = k2 + (long)CSL * C2DV; a.C1 = q2 + (long)CSL * C2DV; a.C2 = v2 + (long)CSL * C2DV;
            a.ldc = C2DV; a.sC = (long)CL * C2DV;
            a.dupC = 1; a.Z = CBH; a.nh = CH; a.groups = 1;
            gemm(CSEG, C2DV, CDV, a);
        }
        {
            GArg a{};
            a.A = att1 + (long)(CSL + CSEG) * CDV; a.lda = CDV; a.sAb = sA1b; a.sAh = sA1h;
            a.B0 = W2kse; a.B1 = W2qse; a.B2 = W2vse; a.ldb = C2DV; a.sBb = 0; a.sBh = W2H; a.transB = 1;
            a.C0 = k2 + (long)(CSL + CSEG) * C2DV; a.C1 = q2 + (long)(CSL + CSEG) * C2DV;
            a.C2 = v2 + (long)(CSL + CSEG) * C2DV; a.ldc = C2DV; a.sC = (long)CL * C2DV;
            a.Z = CBH; a.nh = CH; a.groups = 3;
            gemm(CSL, C2DV, CDV, a);
        }

        // ---- attention 2 (fused, queries 128..767, split store) ----
        {
            dim3 g((CL - CSL) / 128, CBH);
            flash_attn<128><<<g, 256, 768 * (128 + 8) * 2>>>(
                q2 + (long)CSL * C2DV, (long)CL * C2DV,
                k2, (long)CL * C2DV, v2, (long)CL * C2DV,
                a2c, C2DV, (long)CSEG * C2DV,
                a2e, C2DV, (long)CSL * C2DV, CSEG, CSL);
        }

        // ---- output GEMMs ----
        {
            GArg a{};
            a.A = a2c; a.lda = 2 * CH * CDV; a.sAb = (long)CH * CSEG * C2DV; a.sAh = 0;
            a.B0 = Wout; a.ldb = CD; a.sBb = 0; a.sBh = 0; a.transB = 1;
            a.C0 = out + (long)seg * CSEG * CD; a.ldc = CD; a.sC = (long)CS * CD;
            a.Z = CB; a.nh = 1; a.groups = 1;
            gemm(CSEG, CD, 2 * CH * CDV, a);
        }
        {
            float* dst = (seg < 3) ? stb : (out + (long)CB * CS * CD);
            GArg a{};
            a.A = a2e; a.lda = 2 * CH * CDV; a.sAb = (long)CH * CSL * C2DV; a.sAh = 0;
            a.B0 = Wos; a.ldb = CD; a.sBb = 0; a.sBh = 0; a.transB = 1;
            a.C0 = dst; a.ldc = CD; a.sC = (long)CSL * CD;
            a.Z = CB; a.nh = 1; a.groups = 1;
            gemm(CSL, CD, 2 * CH * CDV, a);
        }
    }
}